// round 6
// baseline (speedup 1.0000x reference)
#include <cuda_runtime.h>
#include <math.h>

#define TT 256
#define BB 64
#define DD 1024
#define ND (3*DD)        // 3072
#define MTOT (TT*BB)     // 16384

#define RG 64            // GRU CTAs
#define HELPERS 84       // xproj helper CTAs
#define GRID_ALL (RG + HELPERS)
#define NTILE_N (ND / 128)        // 24
#define NTILE_M (MTOT / 128)      // 128
#define NCHUNK 16                 // K chunks of 64 cols (4 producer CTAs each)

#define NTHREADS 384

// ---------------- scratch ----------------
__device__ float g_xproj[(size_t)MTOT * ND];
__device__ float g_hring[4][BB * DD];          // 4-deep h ring
__device__ unsigned g_ck[NCHUNK];              // monotonic chunk counters
__device__ unsigned g_tilecnt[NTILE_M];

// ---------------- helpers ----------------
__device__ __forceinline__ unsigned f2tf(float x) {
    unsigned y;
    asm("cvt.rna.tf32.f32 %0, %1;" : "=r"(y) : "f"(x));
    return y;
}
__device__ __forceinline__ float f2tf_f(float x) { return __uint_as_float(f2tf(x)); }
__device__ __forceinline__ unsigned fu(float x) { return __float_as_uint(x); }

__device__ __forceinline__ unsigned ld_acq(const unsigned* p) {
    unsigned v;
    asm volatile("ld.acquire.gpu.global.b32 %0, [%1];" : "=r"(v) : "l"(p) : "memory");
    return v;
}
__device__ __forceinline__ void red_rel_add(unsigned* p, unsigned v) {
    asm volatile("red.release.gpu.global.add.u32 [%0], %1;" :: "l"(p), "r"(v) : "memory");
}

__device__ __forceinline__ void mma_tf32(float c[4], const unsigned a[4], const unsigned b[2]) {
    asm volatile(
        "mma.sync.aligned.m16n8k8.row.col.f32.tf32.tf32.f32 "
        "{%0,%1,%2,%3}, {%4,%5,%6,%7}, {%8,%9}, {%0,%1,%2,%3};\n"
        : "+f"(c[0]), "+f"(c[1]), "+f"(c[2]), "+f"(c[3])
        : "r"(a[0]), "r"(a[1]), "r"(a[2]), "r"(a[3]),
          "r"(b[0]), "r"(b[1]));
}

__device__ __forceinline__ bool get_done(const void* p, int idx, int flag) {
    if (flag == 1) return ((const unsigned char*)p)[idx] != 0;
    if (flag == 0) return ((const int*)p)[idx] != 0;
    return ((const float*)p)[idx] != 0.0f;
}

__device__ __forceinline__ float sigmoidf_(float x) {
    return 1.0f / (1.0f + __expf(-x));
}

// ---------------- reset ----------------
__global__ void reset_kernel() {
    int t = threadIdx.x;
    if (t < NCHUNK) g_ck[t] = 0u;
    if (t < NTILE_M) g_tilecnt[t] = 0u;
}

// ---------------- geometry ----------------
#define AK 32
#define AS_S 36
#define BS_S 132
#define RKC 64
#define FPC 16

#define WS_WORDS 49152
#define KSTR 516
#define BUF_WORDS 4128
#define OFF_BUFA WS_WORDS
#define OFF_BUFB (WS_WORDS + BUF_WORDS)
#define OFF_BH   (WS_WORDS + 2 * BUF_WORDS)
#define GRU_SMEM_BYTES ((OFF_BH + 16) * 4)       // 229,696 B
#define PS_S 50

// ---------------- helper path: xproj tiles (8 active warps of 12) ----------------
__device__ void helper_xproj(float* sm, const float* __restrict__ ins,
                             const float* __restrict__ Wi,
                             const float* __restrict__ bi, int hid)
{
    float* As = sm;
    float* Bs = sm + 128 * AS_S;

    int tid  = threadIdx.x;
    int warp = tid >> 5, lane = tid & 31;
    int wm = warp >> 2, wn = warp & 3;
    int g = lane >> 2, tg = lane & 3;
    int ra = tid >> 3;
    int ca = (tid & 7) << 2;
    int rb = tid >> 5;
    int cb = (tid & 31) << 2;
    bool stager = (tid < 256);
    bool mmaer = (warp < 8);

    for (int tile = hid; tile < NTILE_M * NTILE_N; tile += HELPERS) {
        int mb = tile / NTILE_N, nb = tile % NTILE_N;
        int mBase = mb * 128, nBase = nb * 128;

        float acc[4][4][4];
#pragma unroll
        for (int mt = 0; mt < 4; mt++)
#pragma unroll
            for (int nt = 0; nt < 4; nt++)
#pragma unroll
                for (int i = 0; i < 4; i++) acc[mt][nt][i] = 0.0f;

        float4 av[4], bv[4];
        if (stager) {
#pragma unroll
            for (int p = 0; p < 4; p++)
                av[p] = *(const float4*)&ins[(size_t)(mBase + ra + p * 32) * DD + ca];
#pragma unroll
            for (int p = 0; p < 4; p++)
                bv[p] = *(const float4*)&Wi[(size_t)(rb + p * 8) * ND + nBase + cb];
        }

        for (int kb = 0; kb < DD; kb += AK) {
            if (stager) {
#pragma unroll
                for (int p = 0; p < 4; p++) {
                    float* d = &As[(ra + p * 32) * AS_S + ca];
                    d[0] = f2tf_f(av[p].x); d[1] = f2tf_f(av[p].y);
                    d[2] = f2tf_f(av[p].z); d[3] = f2tf_f(av[p].w);
                }
#pragma unroll
                for (int p = 0; p < 4; p++) {
                    float* d = &Bs[(rb + p * 8) * BS_S + cb];
                    d[0] = f2tf_f(bv[p].x); d[1] = f2tf_f(bv[p].y);
                    d[2] = f2tf_f(bv[p].z); d[3] = f2tf_f(bv[p].w);
                }
            }
            __syncthreads();

            if (stager && kb + AK < DD) {
#pragma unroll
                for (int p = 0; p < 4; p++)
                    av[p] = *(const float4*)&ins[(size_t)(mBase + ra + p * 32) * DD + kb + AK + ca];
#pragma unroll
                for (int p = 0; p < 4; p++)
                    bv[p] = *(const float4*)&Wi[(size_t)(kb + AK + rb + p * 8) * ND + nBase + cb];
            }

            if (mmaer) {
#pragma unroll
                for (int kk = 0; kk < AK; kk += 8) {
                    unsigned a[4][4];
#pragma unroll
                    for (int mt = 0; mt < 4; mt++) {
                        int r0 = wm * 64 + mt * 16;
                        a[mt][0] = fu(As[(r0 + g) * AS_S + kk + tg]);
                        a[mt][1] = fu(As[(r0 + 8 + g) * AS_S + kk + tg]);
                        a[mt][2] = fu(As[(r0 + g) * AS_S + kk + 4 + tg]);
                        a[mt][3] = fu(As[(r0 + 8 + g) * AS_S + kk + 4 + tg]);
                    }
                    unsigned b[4][2];
#pragma unroll
                    for (int nt = 0; nt < 4; nt++) {
                        int c0 = wn * 32 + nt * 8;
                        b[nt][0] = fu(Bs[(kk + tg) * BS_S + c0 + g]);
                        b[nt][1] = fu(Bs[(kk + 4 + tg) * BS_S + c0 + g]);
                    }
#pragma unroll
                    for (int mt = 0; mt < 4; mt++)
#pragma unroll
                        for (int nt = 0; nt < 4; nt++)
                            mma_tf32(acc[mt][nt], a[mt], b[nt]);
                }
            }
            __syncthreads();
        }

        if (mmaer) {
#pragma unroll
            for (int mt = 0; mt < 4; mt++) {
#pragma unroll
                for (int nt = 0; nt < 4; nt++) {
                    int col = nBase + wn * 32 + nt * 8 + 2 * tg;
                    float b0 = bi[col], b1 = bi[col + 1];
                    int r0 = mBase + wm * 64 + mt * 16 + g;
                    float2 v0 = make_float2(acc[mt][nt][0] + b0, acc[mt][nt][1] + b1);
                    float2 v1 = make_float2(acc[mt][nt][2] + b0, acc[mt][nt][3] + b1);
                    *(float2*)&g_xproj[(size_t)r0 * ND + col] = v0;
                    *(float2*)&g_xproj[(size_t)(r0 + 8) * ND + col] = v1;
                }
            }
        }
        __syncthreads();
        if (tid == 0) red_rel_add(&g_tilecnt[mb], 1u);
    }
}

// ---------------- fused persistent kernel ----------------
__global__ __launch_bounds__(NTHREADS) void fused_kernel(
    const float* __restrict__ ins, const float* __restrict__ hiddens,
    const void* __restrict__ dones, const float* __restrict__ init_carry,
    const float* __restrict__ Wi, const float* __restrict__ Wh,
    const float* __restrict__ bi, const float* __restrict__ bhn,
    float* __restrict__ out)
{
    extern __shared__ float sm[];
    int bid = blockIdx.x;
    if (bid >= RG) { helper_xproj(sm, ins, Wi, bi, bid - RG); return; }

    float* ws   = sm;
    float* bufA = &sm[OFF_BUFA];
    float* bufB = &sm[OFF_BUFB];
    float* ps   = &sm[OFF_BUFA];      // union with bufA
    float* bh_s = &sm[OFF_BH];

    int tid = threadIdx.x;
    int f0 = bid * FPC;
    int mychunk = bid >> 2;           // (unused name collision avoided)

    int warp = tid >> 5, lane = tid & 31;
    int wm = warp & 3, wn = warp >> 2;
    int lane4 = lane * 4, lane2 = lane * 2;

    // dones-dtype detection
    int dflag;
    {
        int lf = 0, li = 0;
        const float* pf = (const float*)dones;
        const int*   pi = (const int*)dones;
        for (int i = lane; i < 256; i += 32) {
            float v = pf[i];
            if (!(v == 0.0f || v == 1.0f)) lf = 1;
            int w = pi[i];
            if (!(w == 0 || w == 1)) li = 1;
        }
        lf = __any_sync(0xffffffffu, lf);
        li = __any_sync(0xffffffffu, li);
        dflag = (!lf) ? 2 : ((!li) ? 0 : 1);
    }

    // prologue: h(0) own cols -> ring[0]; carry own values in registers
    float he_reg[3];
#pragma unroll
    for (int i = 0; i < 3; i++) {
        int e = tid + i * NTHREADS;
        if (e < 1024) {
            int b = e >> 4, j = e & 15;
            int f = f0 + j;
            bool dn = get_done(dones, b, dflag);
            float v = dn ? hiddens[(size_t)b * DD + f] : init_carry[(size_t)b * DD + f];
            g_hring[0][b * DD + f] = v;
            he_reg[i] = v;
        }
    }
    __syncthreads();
    if (tid == 0) red_rel_add(&g_ck[mychunk], 1u);

    // one-time: W_h slice as fragment-major float2 per lane
    for (int idx = tid; idx < 128 * 6 * 32; idx += NTHREADS) {
        int l = idx & 31;
        int ntwn = (idx >> 5) % 6;
        int kkg = idx / 192;
        int gg = l >> 2, tg2 = l & 3;
        int c = (ntwn >> 1) * 16 + (ntwn & 1) * 8 + gg;
        int gate = c >> 4, j = c & 15;
        size_t colg = (size_t)gate * DD + f0 + j;
        int k0 = kkg * 8 + tg2;
        float v0 = Wh[(size_t)k0 * ND + colg];
        float v1 = Wh[(size_t)(k0 + 4) * ND + colg];
        ws[(size_t)idx * 2 + 0] = f2tf_f(v0);
        ws[(size_t)idx * 2 + 1] = f2tf_f(v1);
    }
    if (tid < 16) bh_s[tid] = bhn[f0 + tid];
    __syncthreads();

    // staging precompute
    int nst = (tid < 256) ? 3 : 2;
    int gofs[3];
    int sofs[3];
#pragma unroll
    for (int i = 0; i < 3; i++) {
        int e = tid + i * NTHREADS;
        if (e >= 1024) e = 1023;
        int r = e >> 4, c = (e & 15) << 2;
        gofs[i] = r * DD + c;
        int wmr = r >> 4, gg = r & 7, half = (r >> 3) & 1;
        int kk = c >> 3, sub = (c >> 2) & 1;
        sofs[i] = kk * KSTR + wmr * 128 + 16 * gg + (half + 2 * sub);
    }

#define WAITC(cidx) { \
    if (lane == 0) { while (ld_acq(&g_ck[(cidx)]) < need) { } } \
    __syncwarp(); }
#define LOADC(dst, cidx) { \
    _Pragma("unroll") \
    for (int i = 0; i < 3; i++) if (i < nst) \
        dst[i] = __ldcg((const float4*)&hsrc[gofs[i] + (cidx) * RKC]); }
#define COMMIT(src, bufp) { \
    _Pragma("unroll") \
    for (int i = 0; i < 3; i++) if (i < nst) { \
        float* d = &(bufp)[sofs[i]]; \
        d[0]  = f2tf_f(src[i].x); d[4]  = f2tf_f(src[i].y); \
        d[8]  = f2tf_f(src[i].z); d[12] = f2tf_f(src[i].w); } }

    for (int t = 0; t < TT; t++) {
        const float* hsrc = g_hring[t & 3];
        float* hdst = g_hring[(t + 1) & 3];
        unsigned need = 4u * (unsigned)(t + 1);

        float acc[2][4];
#pragma unroll
        for (int nt = 0; nt < 2; nt++)
#pragma unroll
            for (int i = 0; i < 4; i++) acc[nt][i] = 0.0f;

        float4 pv0[3], pv1[3];
        WAITC(0); WAITC(1);
        LOADC(pv0, 0);
        LOADC(pv1, 1);

        // xproj tile availability (per-warp acquire poll; cold L1 lines)
        if ((t & 1) == 0) {
            if (lane == 0) {
                while (ld_acq(&g_tilecnt[t >> 1]) < (unsigned)NTILE_N) { }
            }
            __syncwarp();
        }

        // epilogue operand prefetch
        float xr[3], xz[3], xn[3], hv[3];
        int dnp[3];
#pragma unroll
        for (int i = 0; i < 3; i++) {
            int e = tid + i * NTHREADS;
            if (e < 1024) {
                int b = e >> 4, j = e & 15;
                int f = f0 + j;
                const float* xb = &g_xproj[((size_t)t * BB + b) * ND];
                xr[i] = xb[f]; xz[i] = xb[DD + f]; xn[i] = xb[2 * DD + f];
                if (t < TT - 1) {
                    dnp[i] = get_done(dones, (t + 1) * BB + b, dflag) ? 1 : 0;
                    hv[i] = hiddens[((size_t)(t + 1) * BB + b) * DD + f];
                } else { dnp[i] = 0; hv[i] = 0.0f; }
            }
        }

        COMMIT(pv0, bufA);
        WAITC(2);
        LOADC(pv0, 2);
        __syncthreads();

        for (int kb = 0; kb < 16; kb++) {
            float* cbuf = (kb & 1) ? bufB : bufA;
            if (kb + 1 < 16) {
                if (kb & 1) {
                    COMMIT(pv0, bufA);
                    if (kb + 3 < 16) { WAITC(kb + 3); LOADC(pv0, kb + 3); }
                } else {
                    COMMIT(pv1, bufB);
                    if (kb + 3 < 16) { WAITC(kb + 3); LOADC(pv1, kb + 3); }
                }
            }
            int kg0 = kb * 8;
#pragma unroll
            for (int kk = 0; kk < 8; kk++) {
                float4 a4 = *(const float4*)&cbuf[kk * KSTR + wm * 128 + lane4];
#pragma unroll
                for (int nt = 0; nt < 2; nt++) {
                    float2 b2 = *(const float2*)&ws[(size_t)((kg0 + kk) * 6 + wn * 2 + nt) * 64 + lane2];
                    mma_tf32(acc[nt], (const unsigned*)&a4, (const unsigned*)&b2);
                }
            }
            __syncthreads();
        }

        // GEMM result -> ps
        {
            int g = lane >> 2, tg = lane & 3;
            int r0 = wm * 16 + g;
#pragma unroll
            for (int nt = 0; nt < 2; nt++) {
                int c0 = wn * 16 + nt * 8 + 2 * tg;
                ps[r0 * PS_S + c0]           = acc[nt][0];
                ps[r0 * PS_S + c0 + 1]       = acc[nt][1];
                ps[(r0 + 8) * PS_S + c0]     = acc[nt][2];
                ps[(r0 + 8) * PS_S + c0 + 1] = acc[nt][3];
            }
        }
        __syncthreads();

        // gates + update (he carried in registers)
#pragma unroll
        for (int i = 0; i < 3; i++) {
            int e = tid + i * NTHREADS;
            if (e < 1024) {
                int b = e >> 4, j = e & 15;
                int f = f0 + j;
                float r = sigmoidf_(xr[i] + ps[b * PS_S + j]);
                float z = sigmoidf_(xz[i] + ps[b * PS_S + 16 + j]);
                float n = tanhf(xn[i] + r * (ps[b * PS_S + 32 + j] + bh_s[j]));
                float hnew = (1.0f - z) * n + z * he_reg[i];
                out[BB * DD + ((size_t)t * BB + b) * DD + f] = hnew;   // ys
                if (t == TT - 1) {
                    out[(size_t)b * DD + f] = hnew;                     // final_carry
                } else {
                    float nv = dnp[i] ? hv[i] : hnew;
                    hdst[b * DD + f] = nv;
                    he_reg[i] = nv;
                }
            }
        }

        __syncthreads();
        if (tid == 0) red_rel_add(&g_ck[mychunk], 1u);
    }
#undef WAITC
#undef LOADC
#undef COMMIT
}

// ---------------- launch ----------------
extern "C" void kernel_launch(void* const* d_in, const int* in_sizes, int n_in,
                              void* d_out, int out_size) {
    const float* ins        = (const float*)d_in[0];
    const float* hiddens    = (const float*)d_in[1];
    const void*  dones      = (const void*)d_in[2];
    const float* init_carry = (const float*)d_in[3];
    const float* Wi         = (const float*)d_in[4];
    const float* Wh         = (const float*)d_in[5];
    const float* bi         = (const float*)d_in[6];
    const float* bhn        = (const float*)d_in[7];
    float* out = (float*)d_out;

    static int smem_set = 0;
    if (!smem_set) {
        cudaFuncSetAttribute(fused_kernel,
            cudaFuncAttributeMaxDynamicSharedMemorySize, GRU_SMEM_BYTES);
        smem_set = 1;
    }

    reset_kernel<<<1, 128>>>();
    fused_kernel<<<GRID_ALL, NTHREADS, GRU_SMEM_BYTES>>>(
        ins, hiddens, dones, init_carry, Wi, Wh, bi, bhn, out);
}

// round 8
// speedup vs baseline: 1.8368x; 1.8368x over previous
#include <cuda_runtime.h>
#include <cuda_fp16.h>
#include <math.h>

#define TT 256
#define BB 64
#define DD 1024
#define ND (3*DD)        // 3072
#define MTOT (TT*BB)     // 16384

#define RG 64            // GRU CTAs
#define HELPERS 84       // xproj helper CTAs
#define GRID_ALL (RG + HELPERS)
#define NTILE_N (ND / 128)        // 24
#define NTILE_M (MTOT / 128)      // 128

// ---------------- scratch ----------------
__device__ float g_xproj[(size_t)MTOT * ND];
__device__ float g_heff[2][BB * DD];
__device__ unsigned g_count;
__device__ unsigned g_release;
__device__ unsigned g_tilecnt[NTILE_M];

// ---------------- primitives ----------------
__device__ __forceinline__ unsigned f2tf(float x) {
    unsigned y;
    asm("cvt.rna.tf32.f32 %0, %1;" : "=r"(y) : "f"(x));
    return y;
}
__device__ __forceinline__ float f2tf_f(float x) { return __uint_as_float(f2tf(x)); }
__device__ __forceinline__ unsigned fu(float x) { return __float_as_uint(x); }

__device__ __forceinline__ unsigned ld_acq(const unsigned* p) {
    unsigned v;
    asm volatile("ld.acquire.gpu.global.b32 %0, [%1];" : "=r"(v) : "l"(p) : "memory");
    return v;
}
__device__ __forceinline__ void red_rel_add(unsigned* p, unsigned v) {
    asm volatile("red.release.gpu.global.add.u32 [%0], %1;" :: "l"(p), "r"(v) : "memory");
}
__device__ __forceinline__ unsigned atom_rel_add(unsigned* p, unsigned v) {
    unsigned old;
    asm volatile("atom.release.gpu.global.add.u32 %0, [%1], %2;"
                 : "=r"(old) : "l"(p), "r"(v) : "memory");
    return old;
}
__device__ __forceinline__ void st_rel(unsigned* p, unsigned v) {
    asm volatile("st.release.gpu.global.b32 [%0], %1;" :: "l"(p), "r"(v) : "memory");
}

__device__ __forceinline__ void mma_tf32(float c[4], const unsigned a[4], const unsigned b[2]) {
    asm volatile(
        "mma.sync.aligned.m16n8k8.row.col.f32.tf32.tf32.f32 "
        "{%0,%1,%2,%3}, {%4,%5,%6,%7}, {%8,%9}, {%0,%1,%2,%3};\n"
        : "+f"(c[0]), "+f"(c[1]), "+f"(c[2]), "+f"(c[3])
        : "r"(a[0]), "r"(a[1]), "r"(a[2]), "r"(a[3]),
          "r"(b[0]), "r"(b[1]));
}
__device__ __forceinline__ void mma_f16(float c[4], const unsigned a[4], const unsigned b[2]) {
    asm volatile(
        "mma.sync.aligned.m16n8k16.row.col.f32.f16.f16.f32 "
        "{%0,%1,%2,%3}, {%4,%5,%6,%7}, {%8,%9}, {%0,%1,%2,%3};\n"
        : "+f"(c[0]), "+f"(c[1]), "+f"(c[2]), "+f"(c[3])
        : "r"(a[0]), "r"(a[1]), "r"(a[2]), "r"(a[3]),
          "r"(b[0]), "r"(b[1]));
}

__device__ __forceinline__ bool get_done(const void* p, int idx, int flag) {
    if (flag == 1) return ((const unsigned char*)p)[idx] != 0;
    if (flag == 0) return ((const int*)p)[idx] != 0;
    return ((const float*)p)[idx] != 0.0f;
}
__device__ __forceinline__ float sigmoidf_(float x) {
    return 1.0f / (1.0f + __expf(-x));
}

// ---------------- reset ----------------
__global__ void reset_kernel() {
    int t = threadIdx.x;
    if (t == 0) { g_count = 0u; g_release = 0u; }
    if (t < NTILE_M) g_tilecnt[t] = 0u;
}

// ---------------- geometry ----------------
#define AK 32
#define AS_S 36
#define BS_S 132
#define RKC 64
#define FPC 16
#define PS_S 50

// GRU smem layout in u32 words:
//  ws  : 64 kg x 6 ntw x 32 lanes x 2 u32 (b-frags)  = 24576 u32
//  bufA/bufB: 4 kkg-blocks, kkg stride 516 u32        = 2064 u32 each
//  ps (f32 [64][50] = 3200 u32) unions over bufA+bufB (4128)
//  bh  : 16 u32
#define WS_U32   24576
#define KKGSTR   516
#define BUF_U32  2064
#define OFF_BUFA WS_U32
#define OFF_BUFB (WS_U32 + BUF_U32)
#define OFF_BH   (WS_U32 + 2 * BUF_U32)
#define GRU_SMEM_BYTES ((OFF_BH + 16) * 4)    // 114,880 B

__device__ __forceinline__ void grid_barrier(unsigned expected) {
    __syncthreads();
    if (threadIdx.x == 0) {
        unsigned prev = atom_rel_add(&g_count, 1u);
        if (prev + 1u == expected) {
            st_rel(&g_release, expected);
        } else {
            while (ld_acq(&g_release) < expected) { }
        }
    }
    __syncthreads();
}

// ---------------- helper path: xproj tiles (tf32, unchanged structure) ---------
__device__ void helper_xproj(float* sm, const float* __restrict__ ins,
                             const float* __restrict__ Wi,
                             const float* __restrict__ bi, int hid)
{
    float* As = sm;
    float* Bs = sm + 128 * AS_S;

    int tid  = threadIdx.x;
    int warp = tid >> 5, lane = tid & 31;
    int wm = warp >> 2, wn = warp & 3;
    int g = lane >> 2, tg = lane & 3;
    int ra = tid >> 3;
    int ca = (tid & 7) << 2;
    int rb = tid >> 5;
    int cb = (tid & 31) << 2;

    for (int tile = hid; tile < NTILE_M * NTILE_N; tile += HELPERS) {
        int mb = tile / NTILE_N, nb = tile % NTILE_N;
        int mBase = mb * 128, nBase = nb * 128;

        float acc[4][4][4];
#pragma unroll
        for (int mt = 0; mt < 4; mt++)
#pragma unroll
            for (int nt = 0; nt < 4; nt++)
#pragma unroll
                for (int i = 0; i < 4; i++) acc[mt][nt][i] = 0.0f;

        float4 av[4], bv[4];
#pragma unroll
        for (int p = 0; p < 4; p++)
            av[p] = *(const float4*)&ins[(size_t)(mBase + ra + p * 32) * DD + ca];
#pragma unroll
        for (int p = 0; p < 4; p++)
            bv[p] = *(const float4*)&Wi[(size_t)(rb + p * 8) * ND + nBase + cb];

        for (int kb = 0; kb < DD; kb += AK) {
#pragma unroll
            for (int p = 0; p < 4; p++) {
                float* d = &As[(ra + p * 32) * AS_S + ca];
                d[0] = f2tf_f(av[p].x); d[1] = f2tf_f(av[p].y);
                d[2] = f2tf_f(av[p].z); d[3] = f2tf_f(av[p].w);
            }
#pragma unroll
            for (int p = 0; p < 4; p++) {
                float* d = &Bs[(rb + p * 8) * BS_S + cb];
                d[0] = f2tf_f(bv[p].x); d[1] = f2tf_f(bv[p].y);
                d[2] = f2tf_f(bv[p].z); d[3] = f2tf_f(bv[p].w);
            }
            __syncthreads();

            if (kb + AK < DD) {
#pragma unroll
                for (int p = 0; p < 4; p++)
                    av[p] = *(const float4*)&ins[(size_t)(mBase + ra + p * 32) * DD + kb + AK + ca];
#pragma unroll
                for (int p = 0; p < 4; p++)
                    bv[p] = *(const float4*)&Wi[(size_t)(kb + AK + rb + p * 8) * ND + nBase + cb];
            }

#pragma unroll
            for (int kk = 0; kk < AK; kk += 8) {
                unsigned a[4][4];
#pragma unroll
                for (int mt = 0; mt < 4; mt++) {
                    int r0 = wm * 64 + mt * 16;
                    a[mt][0] = fu(As[(r0 + g) * AS_S + kk + tg]);
                    a[mt][1] = fu(As[(r0 + 8 + g) * AS_S + kk + tg]);
                    a[mt][2] = fu(As[(r0 + g) * AS_S + kk + 4 + tg]);
                    a[mt][3] = fu(As[(r0 + 8 + g) * AS_S + kk + 4 + tg]);
                }
                unsigned b[4][2];
#pragma unroll
                for (int nt = 0; nt < 4; nt++) {
                    int c0 = wn * 32 + nt * 8;
                    b[nt][0] = fu(Bs[(kk + tg) * BS_S + c0 + g]);
                    b[nt][1] = fu(Bs[(kk + 4 + tg) * BS_S + c0 + g]);
                }
#pragma unroll
                for (int mt = 0; mt < 4; mt++)
#pragma unroll
                    for (int nt = 0; nt < 4; nt++)
                        mma_tf32(acc[mt][nt], a[mt], b[nt]);
            }
            __syncthreads();
        }

#pragma unroll
        for (int mt = 0; mt < 4; mt++) {
#pragma unroll
            for (int nt = 0; nt < 4; nt++) {
                int col = nBase + wn * 32 + nt * 8 + 2 * tg;
                float b0 = bi[col], b1 = bi[col + 1];
                int r0 = mBase + wm * 64 + mt * 16 + g;
                float2 v0 = make_float2(acc[mt][nt][0] + b0, acc[mt][nt][1] + b1);
                float2 v1 = make_float2(acc[mt][nt][2] + b0, acc[mt][nt][3] + b1);
                *(float2*)&g_xproj[(size_t)r0 * ND + col] = v0;
                *(float2*)&g_xproj[(size_t)(r0 + 8) * ND + col] = v1;
            }
        }
        __syncthreads();
        if (tid == 0) red_rel_add(&g_tilecnt[mb], 1u);
    }
}

// ---------------- fused persistent kernel ----------------
__global__ __launch_bounds__(256) void fused_kernel(
    const float* __restrict__ ins, const float* __restrict__ hiddens,
    const void* __restrict__ dones, const float* __restrict__ init_carry,
    const float* __restrict__ Wi, const float* __restrict__ Wh,
    const float* __restrict__ bi, const float* __restrict__ bhn,
    float* __restrict__ out)
{
    extern __shared__ unsigned smu[];
    int bid = blockIdx.x;
    if (bid >= RG) { helper_xproj((float*)smu, ins, Wi, bi, bid - RG); return; }

    unsigned* ws   = smu;                 // b-fragments (fp16x2 pairs)
    unsigned* bufA = &smu[OFF_BUFA];
    unsigned* bufB = &smu[OFF_BUFB];
    float*    ps   = (float*)&smu[OFF_BUFA];   // union over bufA+bufB
    float*    bh_s = (float*)&smu[OFF_BH];

    int tid = threadIdx.x;
    int f0 = bid * FPC;

    int warp = tid >> 5, lane = tid & 31;
    int wm = warp & 3, wn = warp >> 2;        // wm m-tile (16 rows), wn n-half (24 cols)
    int g = lane >> 2, tg = lane & 3;
    int lane4 = lane * 4;

    // dones-dtype detection (first 1024 bytes; safe for smallest u8 layout)
    int dflag;
    {
        int lf = 0, li = 0;
        const float* pf = (const float*)dones;
        const int*   pi = (const int*)dones;
        for (int i = lane; i < 256; i += 32) {
            float v = pf[i];
            if (!(v == 0.0f || v == 1.0f)) lf = 1;
            int w = pi[i];
            if (!(w == 0 || w == 1)) li = 1;
        }
        lf = __any_sync(0xffffffffu, lf);
        li = __any_sync(0xffffffffu, li);
        dflag = (!lf) ? 2 : ((!li) ? 0 : 1);
    }

    // prologue: h_eff[0] own cols; carry own values in regs
    float he_reg[4];
#pragma unroll
    for (int i = 0; i < 4; i++) {
        int e = tid + i * 256;
        int b = e >> 4, j = e & 15;
        int f = f0 + j;
        bool dn = get_done(dones, b, dflag);
        float v = dn ? hiddens[(size_t)b * DD + f] : init_carry[(size_t)b * DD + f];
        g_heff[0][b * DD + f] = v;
        he_reg[i] = v;
    }

    // one-time: W_h slice as fragment-major fp16 b-frags
    // slot (kg 0..63, ntw 0..5, lane): b0 = (W[k0][c], W[k0+1][c]), b1 = (W[k0+8][c], W[k0+9][c])
    //   c = ntw*8 + (lane>>2), k0 = kg*16 + 2*(lane&3)
    for (int idx = tid; idx < 64 * 6 * 32; idx += 256) {
        int l = idx & 31;
        int ntw = (idx >> 5) % 6;
        int kg = idx / 192;
        int c = ntw * 8 + (l >> 2);
        int gate = c >> 4, j = c & 15;
        size_t colg = (size_t)gate * DD + f0 + j;
        int k0 = kg * 16 + 2 * (l & 3);
        float w0 = Wh[(size_t)k0 * ND + colg];
        float w1 = Wh[(size_t)(k0 + 1) * ND + colg];
        float w2 = Wh[(size_t)(k0 + 8) * ND + colg];
        float w3 = Wh[(size_t)(k0 + 9) * ND + colg];
        __half2 p0 = __floats2half2_rn(w0, w1);
        __half2 p1 = __floats2half2_rn(w2, w3);
        ws[(size_t)idx * 2 + 0] = *(unsigned*)&p0;
        ws[(size_t)idx * 2 + 1] = *(unsigned*)&p1;
    }
    if (tid < 16) bh_s[tid] = bhn[f0 + tid];

    unsigned bar_no = 1;
    grid_barrier(RG * bar_no); bar_no++;

    // staging precompute: thread handles quads e = tid + i*256 (i<4)
    // r = e>>4 (0..63), c = (e&15)*4 (0..60) — fixed c per thread across i
    int gofs[4];
    int sofs[4];
#pragma unroll
    for (int i = 0; i < 4; i++) {
        int e = tid + i * 256;
        int r = e >> 4, c = (e & 15) << 2;
        gofs[i] = r * DD + c;
        sofs[i] = (c >> 4) * KKGSTR + (r >> 4) * 128 + 16 * (r & 7)
                + 4 * ((c & 7) >> 1) + ((r >> 3) & 1) + 2 * ((c >> 3) & 1);
    }

#define LOADC(dst, cidx) { \
    _Pragma("unroll") \
    for (int i = 0; i < 4; i++) \
        dst[i] = __ldcg((const float4*)&hsrc[gofs[i] + (cidx) * RKC]); }
#define COMMIT(src, bufp) { \
    _Pragma("unroll") \
    for (int i = 0; i < 4; i++) { \
        __half2 p0 = __floats2half2_rn(src[i].x, src[i].y); \
        __half2 p1 = __floats2half2_rn(src[i].z, src[i].w); \
        (bufp)[sofs[i]]     = *(unsigned*)&p0; \
        (bufp)[sofs[i] + 4] = *(unsigned*)&p1; } }

    for (int t = 0; t < TT; t++) {
        const float* hsrc = g_heff[t & 1];
        float* hdst = g_heff[(t & 1) ^ 1];

        float acc[3][4];
#pragma unroll
        for (int nt = 0; nt < 3; nt++)
#pragma unroll
            for (int i = 0; i < 4; i++) acc[nt][i] = 0.0f;

        float4 pv0[4], pv1[4];
        LOADC(pv0, 0);
        LOADC(pv1, 1);

        // xproj availability for this t's mblock
        if ((t & 1) == 0) {
            if (tid == 0) {
                while (ld_acq(&g_tilecnt[t >> 1]) < (unsigned)NTILE_N) { }
            }
            __syncthreads();
        }

        // epilogue operand prefetch (overlaps mainloop)
        float xr[4], xz[4], xn[4], hv[4];
        int dnp[4];
#pragma unroll
        for (int i = 0; i < 4; i++) {
            int e = tid + i * 256;
            int b = e >> 4, j = e & 15;
            int f = f0 + j;
            const float* xb = &g_xproj[((size_t)t * BB + b) * ND];
            xr[i] = xb[f]; xz[i] = xb[DD + f]; xn[i] = xb[2 * DD + f];
            if (t < TT - 1) {
                dnp[i] = get_done(dones, (t + 1) * BB + b, dflag) ? 1 : 0;
                hv[i] = hiddens[((size_t)(t + 1) * BB + b) * DD + f];
            } else { dnp[i] = 0; hv[i] = 0.0f; }
        }

        COMMIT(pv0, bufA);
        LOADC(pv0, 2);
        __syncthreads();

        for (int kb = 0; kb < 16; kb++) {
            unsigned* cbuf = (kb & 1) ? bufB : bufA;
            if (kb + 1 < 16) {
                if (kb & 1) { COMMIT(pv0, bufA); if (kb + 3 < 16) LOADC(pv0, kb + 3); }
                else        { COMMIT(pv1, bufB); if (kb + 3 < 16) LOADC(pv1, kb + 3); }
            }
            int kgb = kb * 4;
#pragma unroll
            for (int kkg = 0; kkg < 4; kkg++) {
                uint4 a4 = *(const uint4*)&cbuf[kkg * KKGSTR + wm * 128 + lane4];
#pragma unroll
                for (int nt = 0; nt < 3; nt++) {
                    int ntw = wn * 3 + nt;
                    uint2 b2 = *(const uint2*)&ws[(size_t)(((kgb + kkg) * 6 + ntw) * 32 + lane) * 2];
                    mma_f16(acc[nt], (const unsigned*)&a4, (const unsigned*)&b2);
                }
            }
            __syncthreads();
        }

        // GEMM result -> ps
        {
            int r0 = wm * 16 + g;
#pragma unroll
            for (int nt = 0; nt < 3; nt++) {
                int c0 = wn * 24 + nt * 8 + 2 * tg;
                ps[r0 * PS_S + c0]           = acc[nt][0];
                ps[r0 * PS_S + c0 + 1]       = acc[nt][1];
                ps[(r0 + 8) * PS_S + c0]     = acc[nt][2];
                ps[(r0 + 8) * PS_S + c0 + 1] = acc[nt][3];
            }
        }
        __syncthreads();

        // gates + update (he carried in registers)
#pragma unroll
        for (int i = 0; i < 4; i++) {
            int e = tid + i * 256;
            int b = e >> 4, j = e & 15;
            int f = f0 + j;
            float r = sigmoidf_(xr[i] + ps[b * PS_S + j]);
            float z = sigmoidf_(xz[i] + ps[b * PS_S + 16 + j]);
            float n = tanhf(xn[i] + r * (ps[b * PS_S + 32 + j] + bh_s[j]));
            float hnew = (1.0f - z) * n + z * he_reg[i];
            out[BB * DD + ((size_t)t * BB + b) * DD + f] = hnew;   // ys
            if (t == TT - 1) {
                out[(size_t)b * DD + f] = hnew;                     // final_carry
            } else {
                float nv = dnp[i] ? hv[i] : hnew;
                hdst[b * DD + f] = nv;
                he_reg[i] = nv;
            }
        }

        grid_barrier(RG * bar_no); bar_no++;
    }
#undef LOADC
#undef COMMIT
}

// ---------------- launch ----------------
extern "C" void kernel_launch(void* const* d_in, const int* in_sizes, int n_in,
                              void* d_out, int out_size) {
    const float* ins        = (const float*)d_in[0];
    const float* hiddens    = (const float*)d_in[1];
    const void*  dones      = (const void*)d_in[2];
    const float* init_carry = (const float*)d_in[3];
    const float* Wi         = (const float*)d_in[4];
    const float* Wh         = (const float*)d_in[5];
    const float* bi         = (const float*)d_in[6];
    const float* bhn        = (const float*)d_in[7];
    float* out = (float*)d_out;

    static int smem_set = 0;
    if (!smem_set) {
        cudaFuncSetAttribute(fused_kernel,
            cudaFuncAttributeMaxDynamicSharedMemorySize, GRU_SMEM_BYTES);
        smem_set = 1;
    }

    reset_kernel<<<1, 128>>>();
    fused_kernel<<<GRID_ALL, 256, GRU_SMEM_BYTES>>>(
        ins, hiddens, dones, init_carry, Wi, Wh, bi, bhn, out);
}

// round 9
// speedup vs baseline: 2.4858x; 1.3534x over previous
#include <cuda_runtime.h>
#include <cuda_fp16.h>
#include <math.h>

#define TT 256
#define BB 64
#define DD 1024
#define ND (3*DD)        // 3072
#define MTOT (TT*BB)     // 16384

#define RG 64            // GRU CTAs
#define HELPERS 84       // xproj helper CTAs
#define GRID_ALL (RG + HELPERS)
#define NTILE_N (ND / 128)        // 24
#define NTILE_M (MTOT / 128)      // 128

// ---------------- scratch ----------------
__device__ float g_xproj[(size_t)MTOT * ND];
// h ring in fp16 A-fragment layout: [2][64 kkg][512 u32]
__device__ __align__(16) unsigned g_hfrag[2][64 * 512];
__device__ unsigned g_count;
__device__ unsigned g_release;
__device__ unsigned g_tilecnt[NTILE_M];

// ---------------- primitives ----------------
__device__ __forceinline__ unsigned f2tf(float x) {
    unsigned y;
    asm("cvt.rna.tf32.f32 %0, %1;" : "=r"(y) : "f"(x));
    return y;
}
__device__ __forceinline__ float f2tf_f(float x) { return __uint_as_float(f2tf(x)); }
__device__ __forceinline__ unsigned fu(float x) { return __float_as_uint(x); }

__device__ __forceinline__ unsigned ld_acq(const unsigned* p) {
    unsigned v;
    asm volatile("ld.acquire.gpu.global.b32 %0, [%1];" : "=r"(v) : "l"(p) : "memory");
    return v;
}
__device__ __forceinline__ void red_rel_add(unsigned* p, unsigned v) {
    asm volatile("red.release.gpu.global.add.u32 [%0], %1;" :: "l"(p), "r"(v) : "memory");
}
__device__ __forceinline__ unsigned atom_rel_add(unsigned* p, unsigned v) {
    unsigned old;
    asm volatile("atom.release.gpu.global.add.u32 %0, [%1], %2;"
                 : "=r"(old) : "l"(p), "r"(v) : "memory");
    return old;
}
__device__ __forceinline__ void st_rel(unsigned* p, unsigned v) {
    asm volatile("st.release.gpu.global.b32 [%0], %1;" :: "l"(p), "r"(v) : "memory");
}

__device__ __forceinline__ void mma_tf32(float c[4], const unsigned a[4], const unsigned b[2]) {
    asm volatile(
        "mma.sync.aligned.m16n8k8.row.col.f32.tf32.tf32.f32 "
        "{%0,%1,%2,%3}, {%4,%5,%6,%7}, {%8,%9}, {%0,%1,%2,%3};\n"
        : "+f"(c[0]), "+f"(c[1]), "+f"(c[2]), "+f"(c[3])
        : "r"(a[0]), "r"(a[1]), "r"(a[2]), "r"(a[3]),
          "r"(b[0]), "r"(b[1]));
}
__device__ __forceinline__ void mma_f16(float c[4], const unsigned a[4], const unsigned b[2]) {
    asm volatile(
        "mma.sync.aligned.m16n8k16.row.col.f32.f16.f16.f32 "
        "{%0,%1,%2,%3}, {%4,%5,%6,%7}, {%8,%9}, {%0,%1,%2,%3};\n"
        : "+f"(c[0]), "+f"(c[1]), "+f"(c[2]), "+f"(c[3])
        : "r"(a[0]), "r"(a[1]), "r"(a[2]), "r"(a[3]),
          "r"(b[0]), "r"(b[1]));
}

__device__ __forceinline__ bool get_done(const void* p, int idx, int flag) {
    if (flag == 1) return ((const unsigned char*)p)[idx] != 0;
    if (flag == 0) return ((const int*)p)[idx] != 0;
    return ((const float*)p)[idx] != 0.0f;
}
__device__ __forceinline__ float sigmoidf_(float x) {
    return 1.0f / (1.0f + __expf(-x));
}

// ---------------- reset ----------------
__global__ void reset_kernel() {
    int t = threadIdx.x;
    if (t == 0) { g_count = 0u; g_release = 0u; }
    if (t < NTILE_M) g_tilecnt[t] = 0u;
}

// ---------------- geometry ----------------
#define AK 32
#define AS_S 36
#define BS_S 132
#define FPC 16
#define PS_S 50

// GRU smem (u32 words): ws 24576 | ps 3200 | ps2 3200 | bh 16
#define WS_U32  24576
#define OFF_PS  WS_U32
#define OFF_PS2 (WS_U32 + 3200)
#define OFF_BH  (WS_U32 + 6400)
#define GRU_SMEM_BYTES ((OFF_BH + 16) * 4)   // 123,968 B

__device__ __forceinline__ void grid_barrier(unsigned expected) {
    __syncthreads();
    if (threadIdx.x == 0) {
        unsigned prev = atom_rel_add(&g_count, 1u);
        if (prev + 1u == expected) {
            st_rel(&g_release, expected);
        } else {
            while (ld_acq(&g_release) < expected) { }
        }
    }
    __syncthreads();
}

// ---------------- helper path: xproj tiles (tf32) ----------------
__device__ void helper_xproj(float* sm, const float* __restrict__ ins,
                             const float* __restrict__ Wi,
                             const float* __restrict__ bi, int hid)
{
    float* As = sm;
    float* Bs = sm + 128 * AS_S;

    int tid  = threadIdx.x;
    int warp = tid >> 5, lane = tid & 31;
    int wm = warp >> 2, wn = warp & 3;
    int g = lane >> 2, tg = lane & 3;
    int ra = tid >> 3;
    int ca = (tid & 7) << 2;
    int rb = tid >> 5;
    int cb = (tid & 31) << 2;

    for (int tile = hid; tile < NTILE_M * NTILE_N; tile += HELPERS) {
        int mb = tile / NTILE_N, nb = tile % NTILE_N;
        int mBase = mb * 128, nBase = nb * 128;

        float acc[4][4][4];
#pragma unroll
        for (int mt = 0; mt < 4; mt++)
#pragma unroll
            for (int nt = 0; nt < 4; nt++)
#pragma unroll
                for (int i = 0; i < 4; i++) acc[mt][nt][i] = 0.0f;

        float4 av[4], bv[4];
#pragma unroll
        for (int p = 0; p < 4; p++)
            av[p] = *(const float4*)&ins[(size_t)(mBase + ra + p * 32) * DD + ca];
#pragma unroll
        for (int p = 0; p < 4; p++)
            bv[p] = *(const float4*)&Wi[(size_t)(rb + p * 8) * ND + nBase + cb];

        for (int kb = 0; kb < DD; kb += AK) {
#pragma unroll
            for (int p = 0; p < 4; p++) {
                float* d = &As[(ra + p * 32) * AS_S + ca];
                d[0] = f2tf_f(av[p].x); d[1] = f2tf_f(av[p].y);
                d[2] = f2tf_f(av[p].z); d[3] = f2tf_f(av[p].w);
            }
#pragma unroll
            for (int p = 0; p < 4; p++) {
                float* d = &Bs[(rb + p * 8) * BS_S + cb];
                d[0] = f2tf_f(bv[p].x); d[1] = f2tf_f(bv[p].y);
                d[2] = f2tf_f(bv[p].z); d[3] = f2tf_f(bv[p].w);
            }
            __syncthreads();

            if (kb + AK < DD) {
#pragma unroll
                for (int p = 0; p < 4; p++)
                    av[p] = *(const float4*)&ins[(size_t)(mBase + ra + p * 32) * DD + kb + AK + ca];
#pragma unroll
                for (int p = 0; p < 4; p++)
                    bv[p] = *(const float4*)&Wi[(size_t)(kb + AK + rb + p * 8) * ND + nBase + cb];
            }

#pragma unroll
            for (int kk = 0; kk < AK; kk += 8) {
                unsigned a[4][4];
#pragma unroll
                for (int mt = 0; mt < 4; mt++) {
                    int r0 = wm * 64 + mt * 16;
                    a[mt][0] = fu(As[(r0 + g) * AS_S + kk + tg]);
                    a[mt][1] = fu(As[(r0 + 8 + g) * AS_S + kk + tg]);
                    a[mt][2] = fu(As[(r0 + g) * AS_S + kk + 4 + tg]);
                    a[mt][3] = fu(As[(r0 + 8 + g) * AS_S + kk + 4 + tg]);
                }
                unsigned b[4][2];
#pragma unroll
                for (int nt = 0; nt < 4; nt++) {
                    int c0 = wn * 32 + nt * 8;
                    b[nt][0] = fu(Bs[(kk + tg) * BS_S + c0 + g]);
                    b[nt][1] = fu(Bs[(kk + 4 + tg) * BS_S + c0 + g]);
                }
#pragma unroll
                for (int mt = 0; mt < 4; mt++)
#pragma unroll
                    for (int nt = 0; nt < 4; nt++)
                        mma_tf32(acc[mt][nt], a[mt], b[nt]);
            }
            __syncthreads();
        }

#pragma unroll
        for (int mt = 0; mt < 4; mt++) {
#pragma unroll
            for (int nt = 0; nt < 4; nt++) {
                int col = nBase + wn * 32 + nt * 8 + 2 * tg;
                float b0 = bi[col], b1 = bi[col + 1];
                int r0 = mBase + wm * 64 + mt * 16 + g;
                float2 v0 = make_float2(acc[mt][nt][0] + b0, acc[mt][nt][1] + b1);
                float2 v1 = make_float2(acc[mt][nt][2] + b0, acc[mt][nt][3] + b1);
                *(float2*)&g_xproj[(size_t)r0 * ND + col] = v0;
                *(float2*)&g_xproj[(size_t)(r0 + 8) * ND + col] = v1;
            }
        }
        __syncthreads();
        if (tid == 0) red_rel_add(&g_tilecnt[mb], 1u);
    }
}

// ---------------- fused persistent kernel ----------------
__global__ __launch_bounds__(256) void fused_kernel(
    const float* __restrict__ ins, const float* __restrict__ hiddens,
    const void* __restrict__ dones, const float* __restrict__ init_carry,
    const float* __restrict__ Wi, const float* __restrict__ Wh,
    const float* __restrict__ bi, const float* __restrict__ bhn,
    float* __restrict__ out)
{
    extern __shared__ unsigned smu[];
    int bid = blockIdx.x;
    if (bid >= RG) { helper_xproj((float*)smu, ins, Wi, bi, bid - RG); return; }

    unsigned* ws   = smu;
    float*    ps   = (float*)&smu[OFF_PS];
    float*    ps2  = (float*)&smu[OFF_PS2];
    float*    bh_s = (float*)&smu[OFF_BH];

    int tid = threadIdx.x;
    int f0 = bid * FPC;

    int warp = tid >> 5, lane = tid & 31;
    int wm = warp & 3;            // m-tile (16 rows)
    int kh = warp >> 2;           // k-half (0..1): kkg 0..31 or 32..63
    int g = lane >> 2, tg = lane & 3;

    // dones-dtype detection (first 1024 bytes; safe for smallest u8 layout)
    int dflag;
    {
        int lf = 0, li = 0;
        const float* pf = (const float*)dones;
        const int*   pi = (const int*)dones;
        for (int i = lane; i < 256; i += 32) {
            float v = pf[i];
            if (!(v == 0.0f || v == 1.0f)) lf = 1;
            int w = pi[i];
            if (!(w == 0 || w == 1)) li = 1;
        }
        lf = __any_sync(0xffffffffu, lf);
        li = __any_sync(0xffffffffu, li);
        dflag = (!lf) ? 2 : ((!li) ? 0 : 1);
    }

    // per-thread epilogue slots: u32 idx within this CTA's fragment block
    int idx_s[2], b_s[2], jp_s[2];
#pragma unroll
    for (int i = 0; i < 2; i++) {
        int idx = tid + i * 256;
        int wm_s = idx >> 7, g_s = (idx >> 4) & 7, tg_s = (idx >> 2) & 3;
        int half = idx & 1, sub = (idx >> 1) & 1;
        idx_s[i] = idx;
        b_s[i] = wm_s * 16 + half * 8 + g_s;
        jp_s[i] = sub * 8 + tg_s * 2;
    }

    // prologue: h_eff[0]; carry own values in regs; write ring[0] block
    float he_reg[2][2];
#pragma unroll
    for (int i = 0; i < 2; i++) {
        int b = b_s[i], f = f0 + jp_s[i];
        bool dn = get_done(dones, b, dflag);
        float v0 = dn ? hiddens[(size_t)b * DD + f]     : init_carry[(size_t)b * DD + f];
        float v1 = dn ? hiddens[(size_t)b * DD + f + 1] : init_carry[(size_t)b * DD + f + 1];
        he_reg[i][0] = v0; he_reg[i][1] = v1;
        __half2 p = __floats2half2_rn(v0, v1);
        g_hfrag[0][bid * 512 + idx_s[i]] = *(unsigned*)&p;
    }

    // one-time: W_h slice as fragment-major fp16 b-frags (validated layout)
    for (int idx = tid; idx < 64 * 6 * 32; idx += 256) {
        int l = idx & 31;
        int ntw = (idx >> 5) % 6;
        int kg = idx / 192;
        int c = ntw * 8 + (l >> 2);
        int gate = c >> 4, j = c & 15;
        size_t colg = (size_t)gate * DD + f0 + j;
        int k0 = kg * 16 + 2 * (l & 3);
        float w0 = Wh[(size_t)k0 * ND + colg];
        float w1 = Wh[(size_t)(k0 + 1) * ND + colg];
        float w2 = Wh[(size_t)(k0 + 8) * ND + colg];
        float w3 = Wh[(size_t)(k0 + 9) * ND + colg];
        __half2 p0 = __floats2half2_rn(w0, w1);
        __half2 p1 = __floats2half2_rn(w2, w3);
        ws[(size_t)idx * 2 + 0] = *(unsigned*)&p0;
        ws[(size_t)idx * 2 + 1] = *(unsigned*)&p1;
    }
    if (tid < 16) bh_s[tid] = bhn[f0 + tid];

    unsigned bar_no = 1;
    grid_barrier(RG * bar_no); bar_no++;

    int abase = wm * 32 + lane;     // uint4 index within kkg block
    int khbase = kh * 32;

    for (int t = 0; t < TT; t++) {
        const uint4* rb = (const uint4*)&g_hfrag[t & 1][0];
        unsigned* wr = &g_hfrag[(t + 1) & 1][bid * 512];

        float acc[6][4];
#pragma unroll
        for (int n = 0; n < 6; n++)
#pragma unroll
            for (int i = 0; i < 4; i++) acc[n][i] = 0.0f;

        uint4 bufa[2][8];
#define LDCH(d, ch) { \
    _Pragma("unroll") \
    for (int u = 0; u < 8; u++) \
        bufa[d][u] = __ldcg(&rb[(khbase + (ch) * 8 + u) * 128 + abase]); }

        LDCH(0, 0);

        // xproj availability for this t's mblock (per-warp poll; cold L1 lines)
        if ((t & 1) == 0) {
            if (lane == 0) {
                while (ld_acq(&g_tilecnt[t >> 1]) < (unsigned)NTILE_N) { }
            }
            __syncwarp();
        }

        // epilogue operand prefetch (overlaps mainloop)
        float2 xrv[2], xzv[2], xnv[2], hvv[2];
        int dnp[2];
#pragma unroll
        for (int i = 0; i < 2; i++) {
            int b = b_s[i];
            size_t base = ((size_t)t * BB + b) * ND + f0 + jp_s[i];
            xrv[i] = *(const float2*)&g_xproj[base];
            xzv[i] = *(const float2*)&g_xproj[base + DD];
            xnv[i] = *(const float2*)&g_xproj[base + 2 * DD];
            if (t < TT - 1) {
                dnp[i] = get_done(dones, (t + 1) * BB + b, dflag) ? 1 : 0;
                hvv[i] = *(const float2*)&hiddens[((size_t)(t + 1) * BB + b) * DD + f0 + jp_s[i]];
            } else { dnp[i] = 0; hvv[i] = make_float2(0.f, 0.f); }
        }

        // mainloop: 4 chunks x 8 kkg, double-buffered LDG, NO syncthreads
#pragma unroll
        for (int ch = 0; ch < 4; ch++) {
            if (ch < 3) LDCH((ch + 1) & 1, ch + 1);
#pragma unroll
            for (int u = 0; u < 8; u++) {
                int kkg = khbase + ch * 8 + u;
                uint4 a4 = bufa[ch & 1][u];
#pragma unroll
                for (int ntw = 0; ntw < 6; ntw++) {
                    uint2 b2 = *(const uint2*)&ws[(size_t)((kkg * 6 + ntw) * 32 + lane) * 2];
                    mma_f16(acc[ntw], (const unsigned*)&a4, (const unsigned*)&b2);
                }
            }
        }
#undef LDCH

        // partial-sum stores: kh=0 -> ps, kh=1 -> ps2
        {
            float* dst = kh ? ps2 : ps;
            int r0 = wm * 16 + g;
#pragma unroll
            for (int ntw = 0; ntw < 6; ntw++) {
                int c0 = ntw * 8 + 2 * tg;
                dst[r0 * PS_S + c0]           = acc[ntw][0];
                dst[r0 * PS_S + c0 + 1]       = acc[ntw][1];
                dst[(r0 + 8) * PS_S + c0]     = acc[ntw][2];
                dst[(r0 + 8) * PS_S + c0 + 1] = acc[ntw][3];
            }
        }
        __syncthreads();

        // gates + update (he carried in registers; ps+ps2 combined here)
#pragma unroll
        for (int i = 0; i < 2; i++) {
            int b = b_s[i], j = jp_s[i];
            int rb0 = b * PS_S;
            float pr0 = ps[rb0 + j]      + ps2[rb0 + j];
            float pr1 = ps[rb0 + j + 1]  + ps2[rb0 + j + 1];
            float pz0 = ps[rb0 + 16 + j]     + ps2[rb0 + 16 + j];
            float pz1 = ps[rb0 + 16 + j + 1] + ps2[rb0 + 16 + j + 1];
            float pn0 = ps[rb0 + 32 + j]     + ps2[rb0 + 32 + j];
            float pn1 = ps[rb0 + 32 + j + 1] + ps2[rb0 + 32 + j + 1];

            float r0 = sigmoidf_(xrv[i].x + pr0);
            float r1 = sigmoidf_(xrv[i].y + pr1);
            float z0 = sigmoidf_(xzv[i].x + pz0);
            float z1 = sigmoidf_(xzv[i].y + pz1);
            float n0 = tanhf(xnv[i].x + r0 * (pn0 + bh_s[j]));
            float n1 = tanhf(xnv[i].y + r1 * (pn1 + bh_s[j + 1]));
            float h0 = (1.0f - z0) * n0 + z0 * he_reg[i][0];
            float h1 = (1.0f - z1) * n1 + z1 * he_reg[i][1];

            int f = f0 + j;
            *(float2*)&out[BB * DD + ((size_t)t * BB + b) * DD + f] = make_float2(h0, h1);  // ys
            if (t == TT - 1) {
                *(float2*)&out[(size_t)b * DD + f] = make_float2(h0, h1);                    // final_carry
            } else {
                float nv0 = dnp[i] ? hvv[i].x : h0;
                float nv1 = dnp[i] ? hvv[i].y : h1;
                __half2 p = __floats2half2_rn(nv0, nv1);
                wr[idx_s[i]] = *(unsigned*)&p;
                he_reg[i][0] = nv0; he_reg[i][1] = nv1;
            }
        }

        if (t < TT - 1) { grid_barrier(RG * bar_no); bar_no++; }
    }
}

// ---------------- launch ----------------
extern "C" void kernel_launch(void* const* d_in, const int* in_sizes, int n_in,
                              void* d_out, int out_size) {
    const float* ins        = (const float*)d_in[0];
    const float* hiddens    = (const float*)d_in[1];
    const void*  dones      = (const void*)d_in[2];
    const float* init_carry = (const float*)d_in[3];
    const float* Wi         = (const float*)d_in[4];
    const float* Wh         = (const float*)d_in[5];
    const float* bi         = (const float*)d_in[6];
    const float* bhn        = (const float*)d_in[7];
    float* out = (float*)d_out;

    static int smem_set = 0;
    if (!smem_set) {
        cudaFuncSetAttribute(fused_kernel,
            cudaFuncAttributeMaxDynamicSharedMemorySize, GRU_SMEM_BYTES);
        smem_set = 1;
    }

    reset_kernel<<<1, 128>>>();
    fused_kernel<<<GRID_ALL, 256, GRU_SMEM_BYTES>>>(
        ins, hiddens, dones, init_carry, Wi, Wh, bi, bhn, out);
}

// round 10
// speedup vs baseline: 2.5922x; 1.0428x over previous
#include <cuda_runtime.h>
#include <cuda_fp16.h>
#include <math.h>

#define TT 256
#define BB 64
#define DD 1024
#define ND (3*DD)        // 3072
#define MTOT (TT*BB)     // 16384

#define RG 128           // phase-2 recurrence CTAs
#define GRID_ALL 148     // one full wave
#define NTILE_N (ND / 128)        // 24
#define NTILE_M (MTOT / 128)      // 128
#define NTILES (NTILE_M * NTILE_N) // 3072

// ---------------- scratch ----------------
__device__ float g_xproj[(size_t)MTOT * ND];
// h ring in fp16 A-fragment layout: [2][64 kkg][512 u32]
__device__ __align__(16) unsigned g_hfrag[2][64 * 512];
__device__ unsigned g_count;
__device__ unsigned g_release;

// ---------------- primitives ----------------
__device__ __forceinline__ unsigned f2tf(float x) {
    unsigned y;
    asm("cvt.rna.tf32.f32 %0, %1;" : "=r"(y) : "f"(x));
    return y;
}
__device__ __forceinline__ float f2tf_f(float x) { return __uint_as_float(f2tf(x)); }
__device__ __forceinline__ unsigned fu(float x) { return __float_as_uint(x); }

__device__ __forceinline__ unsigned ld_acq(const unsigned* p) {
    unsigned v;
    asm volatile("ld.acquire.gpu.global.b32 %0, [%1];" : "=r"(v) : "l"(p) : "memory");
    return v;
}
__device__ __forceinline__ unsigned atom_rel_add(unsigned* p, unsigned v) {
    unsigned old;
    asm volatile("atom.release.gpu.global.add.u32 %0, [%1], %2;"
                 : "=r"(old) : "l"(p), "r"(v) : "memory");
    return old;
}
__device__ __forceinline__ void st_rel(unsigned* p, unsigned v) {
    asm volatile("st.release.gpu.global.b32 [%0], %1;" :: "l"(p), "r"(v) : "memory");
}

__device__ __forceinline__ void mma_tf32(float c[4], const unsigned a[4], const unsigned b[2]) {
    asm volatile(
        "mma.sync.aligned.m16n8k8.row.col.f32.tf32.tf32.f32 "
        "{%0,%1,%2,%3}, {%4,%5,%6,%7}, {%8,%9}, {%0,%1,%2,%3};\n"
        : "+f"(c[0]), "+f"(c[1]), "+f"(c[2]), "+f"(c[3])
        : "r"(a[0]), "r"(a[1]), "r"(a[2]), "r"(a[3]),
          "r"(b[0]), "r"(b[1]));
}
__device__ __forceinline__ void mma_f16(float c[4], const unsigned a[4], const unsigned b[2]) {
    asm volatile(
        "mma.sync.aligned.m16n8k16.row.col.f32.f16.f16.f32 "
        "{%0,%1,%2,%3}, {%4,%5,%6,%7}, {%8,%9}, {%0,%1,%2,%3};\n"
        : "+f"(c[0]), "+f"(c[1]), "+f"(c[2]), "+f"(c[3])
        : "r"(a[0]), "r"(a[1]), "r"(a[2]), "r"(a[3]),
          "r"(b[0]), "r"(b[1]));
}

__device__ __forceinline__ bool get_done(const void* p, int idx, int flag) {
    if (flag == 1) return ((const unsigned char*)p)[idx] != 0;
    if (flag == 0) return ((const int*)p)[idx] != 0;
    return ((const float*)p)[idx] != 0.0f;
}
__device__ __forceinline__ float sigmoidf_(float x) {
    return 1.0f / (1.0f + __expf(-x));
}

// ---------------- reset ----------------
__global__ void reset_kernel() {
    g_count = 0u;
    g_release = 0u;
}

// ---------------- geometry ----------------
#define AK 32
#define AS_S 36
#define BS_S 132
#define FPC 8            // features per recurrence CTA

// phase-2 smem (u32 words): ws 12288 | ps 64*26 | ps2 64*26 | bh 8
#define WS_U32  12288
#define PS2_S   26
#define OFF_PS  WS_U32
#define OFF_PS2 (WS_U32 + BB * PS2_S)
#define OFF_BH  (WS_U32 + 2 * BB * PS2_S)
#define SMEM_WORDS (OFF_BH + 8)
#define SMEM_BYTES (SMEM_WORDS * 4)          // 62,496 B (covers phase-1's 35 KB too)

__device__ __forceinline__ void grid_barrier(unsigned expected) {
    __syncthreads();
    if (threadIdx.x == 0) {
        unsigned prev = atom_rel_add(&g_count, 1u);
        if (prev + 1u == expected) {
            st_rel(&g_release, expected);
        } else {
            while (ld_acq(&g_release) < expected) { }
        }
    }
    __syncthreads();
}

// ---------------- phase 1: xproj tiles (tf32, all CTAs) ----------------
__device__ void phase1_xproj(float* sm, const float* __restrict__ ins,
                             const float* __restrict__ Wi,
                             const float* __restrict__ bi, int bid)
{
    float* As = sm;                    // 128*36
    float* Bs = sm + 128 * AS_S;       // 32*132

    int tid  = threadIdx.x;
    int warp = tid >> 5, lane = tid & 31;
    int wm = warp >> 2, wn = warp & 3;
    int g = lane >> 2, tg = lane & 3;
    int ra = tid >> 3;
    int ca = (tid & 7) << 2;
    int rb = tid >> 5;
    int cb = (tid & 31) << 2;

    for (int tile = bid; tile < NTILES; tile += GRID_ALL) {
        int mb = tile / NTILE_N, nb = tile % NTILE_N;
        int mBase = mb * 128, nBase = nb * 128;

        float acc[4][4][4];
#pragma unroll
        for (int mt = 0; mt < 4; mt++)
#pragma unroll
            for (int nt = 0; nt < 4; nt++)
#pragma unroll
                for (int i = 0; i < 4; i++) acc[mt][nt][i] = 0.0f;

        float4 av[4], bv[4];
#pragma unroll
        for (int p = 0; p < 4; p++)
            av[p] = *(const float4*)&ins[(size_t)(mBase + ra + p * 32) * DD + ca];
#pragma unroll
        for (int p = 0; p < 4; p++)
            bv[p] = *(const float4*)&Wi[(size_t)(rb + p * 8) * ND + nBase + cb];

        for (int kb = 0; kb < DD; kb += AK) {
#pragma unroll
            for (int p = 0; p < 4; p++) {
                float* d = &As[(ra + p * 32) * AS_S + ca];
                d[0] = f2tf_f(av[p].x); d[1] = f2tf_f(av[p].y);
                d[2] = f2tf_f(av[p].z); d[3] = f2tf_f(av[p].w);
            }
#pragma unroll
            for (int p = 0; p < 4; p++) {
                float* d = &Bs[(rb + p * 8) * BS_S + cb];
                d[0] = f2tf_f(bv[p].x); d[1] = f2tf_f(bv[p].y);
                d[2] = f2tf_f(bv[p].z); d[3] = f2tf_f(bv[p].w);
            }
            __syncthreads();

            if (kb + AK < DD) {
#pragma unroll
                for (int p = 0; p < 4; p++)
                    av[p] = *(const float4*)&ins[(size_t)(mBase + ra + p * 32) * DD + kb + AK + ca];
#pragma unroll
                for (int p = 0; p < 4; p++)
                    bv[p] = *(const float4*)&Wi[(size_t)(kb + AK + rb + p * 8) * ND + nBase + cb];
            }

#pragma unroll
            for (int kk = 0; kk < AK; kk += 8) {
                unsigned a[4][4];
#pragma unroll
                for (int mt = 0; mt < 4; mt++) {
                    int r0 = wm * 64 + mt * 16;
                    a[mt][0] = fu(As[(r0 + g) * AS_S + kk + tg]);
                    a[mt][1] = fu(As[(r0 + 8 + g) * AS_S + kk + tg]);
                    a[mt][2] = fu(As[(r0 + g) * AS_S + kk + 4 + tg]);
                    a[mt][3] = fu(As[(r0 + 8 + g) * AS_S + kk + 4 + tg]);
                }
                unsigned b[4][2];
#pragma unroll
                for (int nt = 0; nt < 4; nt++) {
                    int c0 = wn * 32 + nt * 8;
                    b[nt][0] = fu(Bs[(kk + tg) * BS_S + c0 + g]);
                    b[nt][1] = fu(Bs[(kk + 4 + tg) * BS_S + c0 + g]);
                }
#pragma unroll
                for (int mt = 0; mt < 4; mt++)
#pragma unroll
                    for (int nt = 0; nt < 4; nt++)
                        mma_tf32(acc[mt][nt], a[mt], b[nt]);
            }
            __syncthreads();
        }

#pragma unroll
        for (int mt = 0; mt < 4; mt++) {
#pragma unroll
            for (int nt = 0; nt < 4; nt++) {
                int col = nBase + wn * 32 + nt * 8 + 2 * tg;
                float b0 = bi[col], b1 = bi[col + 1];
                int r0 = mBase + wm * 64 + mt * 16 + g;
                float2 v0 = make_float2(acc[mt][nt][0] + b0, acc[mt][nt][1] + b1);
                float2 v1 = make_float2(acc[mt][nt][2] + b0, acc[mt][nt][3] + b1);
                *(float2*)&g_xproj[(size_t)r0 * ND + col] = v0;
                *(float2*)&g_xproj[(size_t)(r0 + 8) * ND + col] = v1;
            }
        }
        __syncthreads();
    }
}

// ---------------- fused persistent kernel ----------------
__global__ __launch_bounds__(256) void fused_kernel(
    const float* __restrict__ ins, const float* __restrict__ hiddens,
    const void* __restrict__ dones, const float* __restrict__ init_carry,
    const float* __restrict__ Wi, const float* __restrict__ Wh,
    const float* __restrict__ bi, const float* __restrict__ bhn,
    float* __restrict__ out)
{
    extern __shared__ unsigned smu[];
    int bid = blockIdx.x;
    int tid = threadIdx.x;

    int warp = tid >> 5, lane = tid & 31;

    // dones-dtype detection (first 1024 bytes; safe for smallest u8 layout)
    int dflag;
    {
        int lf = 0, li = 0;
        const float* pf = (const float*)dones;
        const int*   pi = (const int*)dones;
        for (int i = lane; i < 256; i += 32) {
            float v = pf[i];
            if (!(v == 0.0f || v == 1.0f)) lf = 1;
            int w = pi[i];
            if (!(w == 0 || w == 1)) li = 1;
        }
        lf = __any_sync(0xffffffffu, lf);
        li = __any_sync(0xffffffffu, li);
        dflag = (!lf) ? 2 : ((!li) ? 0 : 1);
    }

    // recurrence geometry (valid when bid < RG)
    int f0 = bid * FPC;
    int sub = bid & 1;            // which half of the k-group this CTA's features are
    int kgown = bid >> 1;         // k-group (fragment block) index

    // per-thread epilogue slot: one (b, feature-pair)
    int b_s = tid >> 2;
    int jp_s = (tid & 3) << 1;                    // 0,2,4,6
    int idx_s;
    {
        int half = (b_s >> 3) & 1, g_s = b_s & 7, wm_s = b_s >> 4;
        int tg_s = jp_s >> 1;
        idx_s = wm_s * 128 + g_s * 16 + tg_s * 4 + sub * 2 + half;
    }

    // prologue: h_eff[0]; carry own pair in regs; write ring[0] slice
    float he0 = 0.f, he1 = 0.f;
    if (bid < RG) {
        int b = b_s, f = f0 + jp_s;
        bool dn = get_done(dones, b, dflag);
        float v0 = dn ? hiddens[(size_t)b * DD + f]     : init_carry[(size_t)b * DD + f];
        float v1 = dn ? hiddens[(size_t)b * DD + f + 1] : init_carry[(size_t)b * DD + f + 1];
        he0 = v0; he1 = v1;
        __half2 p = __floats2half2_rn(v0, v1);
        g_hfrag[0][kgown * 512 + idx_s] = *(unsigned*)&p;
    }

    // ---------------- phase 1: everyone does xproj ----------------
    phase1_xproj((float*)smu, ins, Wi, bi, bid);

    grid_barrier(GRID_ALL);
    if (bid >= RG) return;

    // ---------------- phase 2 setup ----------------
    unsigned* ws   = smu;                       // b-frags: 64 kg x 3 ntw x 32 lanes x 2 u32
    float*    ps   = (float*)&smu[OFF_PS];
    float*    ps2  = (float*)&smu[OFF_PS2];
    float*    bh_s = (float*)&smu[OFF_BH];

    int wm = warp & 3;            // m-tile (16 rows)
    int kh = warp >> 2;           // k-half: kkg 0..31 / 32..63
    int g = lane >> 2, tg = lane & 3;

    // one-time: W_h slice (24 cols) as fragment-major fp16 b-frags
    for (int idx = tid; idx < 64 * 3 * 32; idx += 256) {
        int l = idx & 31;
        int ntw = (idx >> 5) % 3;
        int kg = idx / 96;
        int c = ntw * 8 + (l >> 2);           // 0..23
        int gate = c >> 3, j = c & 7;
        size_t colg = (size_t)gate * DD + f0 + j;
        int k0 = kg * 16 + 2 * (l & 3);
        float w0 = Wh[(size_t)k0 * ND + colg];
        float w1 = Wh[(size_t)(k0 + 1) * ND + colg];
        float w2 = Wh[(size_t)(k0 + 8) * ND + colg];
        float w3 = Wh[(size_t)(k0 + 9) * ND + colg];
        __half2 p0 = __floats2half2_rn(w0, w1);
        __half2 p1 = __floats2half2_rn(w2, w3);
        ws[(size_t)idx * 2 + 0] = *(unsigned*)&p0;
        ws[(size_t)idx * 2 + 1] = *(unsigned*)&p1;
    }
    if (tid < 8) bh_s[tid] = bhn[f0 + tid];
    __syncthreads();

    int abase = wm * 32 + lane;     // uint4 index within a kkg block
    int khbase = kh * 32;
    unsigned bar_base = GRID_ALL;

    for (int t = 0; t < TT; t++) {
        const uint4* rbuf = (const uint4*)&g_hfrag[t & 1][0];
        unsigned* wr = &g_hfrag[(t + 1) & 1][kgown * 512];

        float acc[3][4];
#pragma unroll
        for (int n = 0; n < 3; n++)
#pragma unroll
            for (int i = 0; i < 4; i++) acc[n][i] = 0.0f;

        uint4 bufa[2][8];
#define LDCH(d, ch) { \
    _Pragma("unroll") \
    for (int u = 0; u < 8; u++) \
        bufa[d][u] = __ldcg(&rbuf[(khbase + (ch) * 8 + u) * 128 + abase]); }

        LDCH(0, 0);

        // epilogue operand prefetch (overlaps mainloop)
        float2 xrv, xzv, xnv, hvv;
        int dnp;
        {
            int b = b_s;
            size_t base = ((size_t)t * BB + b) * ND + f0 + jp_s;
            xrv = *(const float2*)&g_xproj[base];
            xzv = *(const float2*)&g_xproj[base + DD];
            xnv = *(const float2*)&g_xproj[base + 2 * DD];
            if (t < TT - 1) {
                dnp = get_done(dones, (t + 1) * BB + b, dflag) ? 1 : 0;
                hvv = *(const float2*)&hiddens[((size_t)(t + 1) * BB + b) * DD + f0 + jp_s];
            } else { dnp = 0; hvv = make_float2(0.f, 0.f); }
        }

        // mainloop: 4 chunks x 8 kkg, double-buffered LDG, no syncthreads
#pragma unroll
        for (int ch = 0; ch < 4; ch++) {
            if (ch < 3) LDCH((ch + 1) & 1, ch + 1);
#pragma unroll
            for (int u = 0; u < 8; u++) {
                int kkg = khbase + ch * 8 + u;
                uint4 a4 = bufa[ch & 1][u];
#pragma unroll
                for (int ntw = 0; ntw < 3; ntw++) {
                    uint2 b2 = *(const uint2*)&ws[(size_t)((kkg * 3 + ntw) * 32 + lane) * 2];
                    mma_f16(acc[ntw], (const unsigned*)&a4, (const unsigned*)&b2);
                }
            }
        }
#undef LDCH

        // partial-sum stores: kh=0 -> ps, kh=1 -> ps2
        {
            float* dst = kh ? ps2 : ps;
            int r0 = wm * 16 + g;
#pragma unroll
            for (int ntw = 0; ntw < 3; ntw++) {
                int c0 = ntw * 8 + 2 * tg;
                dst[r0 * PS2_S + c0]           = acc[ntw][0];
                dst[r0 * PS2_S + c0 + 1]       = acc[ntw][1];
                dst[(r0 + 8) * PS2_S + c0]     = acc[ntw][2];
                dst[(r0 + 8) * PS2_S + c0 + 1] = acc[ntw][3];
            }
        }
        __syncthreads();

        // gates + update (one feature-pair per thread)
        {
            int b = b_s, j = jp_s;
            int rb0 = b * PS2_S;
            float pr0 = ps[rb0 + j]          + ps2[rb0 + j];
            float pr1 = ps[rb0 + j + 1]      + ps2[rb0 + j + 1];
            float pz0 = ps[rb0 + 8 + j]      + ps2[rb0 + 8 + j];
            float pz1 = ps[rb0 + 8 + j + 1]  + ps2[rb0 + 8 + j + 1];
            float pn0 = ps[rb0 + 16 + j]     + ps2[rb0 + 16 + j];
            float pn1 = ps[rb0 + 16 + j + 1] + ps2[rb0 + 16 + j + 1];

            float r0 = sigmoidf_(xrv.x + pr0);
            float r1 = sigmoidf_(xrv.y + pr1);
            float z0 = sigmoidf_(xzv.x + pz0);
            float z1 = sigmoidf_(xzv.y + pz1);
            float n0 = tanhf(xnv.x + r0 * (pn0 + bh_s[j]));
            float n1 = tanhf(xnv.y + r1 * (pn1 + bh_s[j + 1]));
            float h0 = (1.0f - z0) * n0 + z0 * he0;
            float h1 = (1.0f - z1) * n1 + z1 * he1;

            int f = f0 + j;
            *(float2*)&out[BB * DD + ((size_t)t * BB + b) * DD + f] = make_float2(h0, h1);  // ys
            if (t == TT - 1) {
                *(float2*)&out[(size_t)b * DD + f] = make_float2(h0, h1);                    // final_carry
            } else {
                float nv0 = dnp ? hvv.x : h0;
                float nv1 = dnp ? hvv.y : h1;
                __half2 p = __floats2half2_rn(nv0, nv1);
                wr[idx_s] = *(unsigned*)&p;
                he0 = nv0; he1 = nv1;
            }
        }

        if (t < TT - 1) grid_barrier(bar_base + (unsigned)RG * (unsigned)(t + 1));
    }
}

// ---------------- launch ----------------
extern "C" void kernel_launch(void* const* d_in, const int* in_sizes, int n_in,
                              void* d_out, int out_size) {
    const float* ins        = (const float*)d_in[0];
    const float* hiddens    = (const float*)d_in[1];
    const void*  dones      = (const void*)d_in[2];
    const float* init_carry = (const float*)d_in[3];
    const float* Wi         = (const float*)d_in[4];
    const float* Wh         = (const float*)d_in[5];
    const float* bi         = (const float*)d_in[6];
    const float* bhn        = (const float*)d_in[7];
    float* out = (float*)d_out;

    static int smem_set = 0;
    if (!smem_set) {
        cudaFuncSetAttribute(fused_kernel,
            cudaFuncAttributeMaxDynamicSharedMemorySize, SMEM_BYTES);
        smem_set = 1;
    }

    reset_kernel<<<1, 1>>>();
    fused_kernel<<<GRID_ALL, 256, SMEM_BYTES>>>(
        ins, hiddens, dones, init_carry, Wi, Wh, bi, bhn, out);
}

// round 13
// speedup vs baseline: 2.8732x; 1.1084x over previous
#include <cuda_runtime.h>
#include <cuda_fp16.h>
#include <math.h>

#define TT 256
#define BB 64
#define DD 1024
#define ND (3*DD)        // 3072
#define MTOT (TT*BB)     // 16384

#define RG 128           // phase-2 recurrence CTAs
#define GRID_ALL 148     // one full wave
#define NTILE_N (ND / 128)        // 24
#define NTILE_M (MTOT / 128)      // 128
#define NTILES (NTILE_M * NTILE_N) // 3072

// ---------------- scratch ----------------
__device__ float g_xproj[(size_t)MTOT * ND];
// h ring in fp16 A-fragment layout: [2][64 kkg][512 u32]
__device__ __align__(16) unsigned g_hfrag[2][64 * 512];
__device__ unsigned g_count;
__device__ unsigned g_release;
__device__ unsigned g_cnt16[16 * 32];   // distributed arrival counters (128B apart)

// ---------------- primitives ----------------
__device__ __forceinline__ unsigned f2tf(float x) {
    unsigned y;
    asm("cvt.rna.tf32.f32 %0, %1;" : "=r"(y) : "f"(x));
    return y;
}
__device__ __forceinline__ float f2tf_f(float x) { return __uint_as_float(f2tf(x)); }
__device__ __forceinline__ unsigned fu(float x) { return __float_as_uint(x); }

__device__ __forceinline__ unsigned ld_acq(const unsigned* p) {
    unsigned v;
    asm volatile("ld.acquire.gpu.global.b32 %0, [%1];" : "=r"(v) : "l"(p) : "memory");
    return v;
}
__device__ __forceinline__ void red_rel_add(unsigned* p, unsigned v) {
    asm volatile("red.release.gpu.global.add.u32 [%0], %1;" :: "l"(p), "r"(v) : "memory");
}
__device__ __forceinline__ unsigned atom_rel_add(unsigned* p, unsigned v) {
    unsigned old;
    asm volatile("atom.release.gpu.global.add.u32 %0, [%1], %2;"
                 : "=r"(old) : "l"(p), "r"(v) : "memory");
    return old;
}
__device__ __forceinline__ void st_rel(unsigned* p, unsigned v) {
    asm volatile("st.release.gpu.global.b32 [%0], %1;" :: "l"(p), "r"(v) : "memory");
}

__device__ __forceinline__ void mma_tf32(float c[4], const unsigned a[4], const unsigned b[2]) {
    asm volatile(
        "mma.sync.aligned.m16n8k8.row.col.f32.tf32.tf32.f32 "
        "{%0,%1,%2,%3}, {%4,%5,%6,%7}, {%8,%9}, {%0,%1,%2,%3};\n"
        : "+f"(c[0]), "+f"(c[1]), "+f"(c[2]), "+f"(c[3])
        : "r"(a[0]), "r"(a[1]), "r"(a[2]), "r"(a[3]),
          "r"(b[0]), "r"(b[1]));
}
__device__ __forceinline__ void mma_f16(float c[4], const unsigned a[4], const unsigned b[2]) {
    asm volatile(
        "mma.sync.aligned.m16n8k16.row.col.f32.f16.f16.f32 "
        "{%0,%1,%2,%3}, {%4,%5,%6,%7}, {%8,%9}, {%0,%1,%2,%3};\n"
        : "+f"(c[0]), "+f"(c[1]), "+f"(c[2]), "+f"(c[3])
        : "r"(a[0]), "r"(a[1]), "r"(a[2]), "r"(a[3]),
          "r"(b[0]), "r"(b[1]));
}

__device__ __forceinline__ bool get_done(const void* p, int idx, int flag) {
    if (flag == 1) return ((const unsigned char*)p)[idx] != 0;
    if (flag == 0) return ((const int*)p)[idx] != 0;
    return ((const float*)p)[idx] != 0.0f;
}
__device__ __forceinline__ float sigmoidf_(float x) {
    return 1.0f / (1.0f + __expf(-x));
}

// ---------------- reset ----------------
__global__ void reset_kernel() {
    int t = threadIdx.x;
    if (t == 0) { g_count = 0u; g_release = 0u; }
    if (t < 16) g_cnt16[t * 32] = 0u;
}

// ---------------- geometry ----------------
#define AK 32
#define AS_S 36
#define BS_S 132
#define FPC 8            // features per recurrence CTA

// phase-2 smem (u32 words): ws 12288 | ps 64*26 | ps2 64*26 | bh 8
#define WS_U32  12288
#define PS2_S   26
#define OFF_PS  WS_U32
#define OFF_PS2 (WS_U32 + BB * PS2_S)
#define OFF_BH  (WS_U32 + 2 * BB * PS2_S)
#define SMEM_WORDS (OFF_BH + 8)
#define SMEM_BYTES (SMEM_WORDS * 4)          // 62,496 B (covers phase-1's 35 KB too)

__device__ __forceinline__ void grid_barrier(unsigned expected) {
    __syncthreads();
    if (threadIdx.x == 0) {
        unsigned prev = atom_rel_add(&g_count, 1u);
        if (prev + 1u == expected) {
            st_rel(&g_release, expected);
        } else {
            while (ld_acq(&g_release) < expected) { }
        }
    }
    __syncthreads();
}

// ---------------- phase 1: xproj tiles (tf32, all CTAs) ----------------
__device__ void phase1_xproj(float* sm, const float* __restrict__ ins,
                             const float* __restrict__ Wi,
                             const float* __restrict__ bi, int bid)
{
    float* As = sm;                    // 128*36
    float* Bs = sm + 128 * AS_S;       // 32*132

    int tid  = threadIdx.x;
    int warp = tid >> 5, lane = tid & 31;
    int wm = warp >> 2, wn = warp & 3;
    int g = lane >> 2, tg = lane & 3;
    int ra = tid >> 3;
    int ca = (tid & 7) << 2;
    int rb = tid >> 5;
    int cb = (tid & 31) << 2;

    for (int tile = bid; tile < NTILES; tile += GRID_ALL) {
        int mb = tile / NTILE_N, nb = tile % NTILE_N;
        int mBase = mb * 128, nBase = nb * 128;

        float acc[4][4][4];
#pragma unroll
        for (int mt = 0; mt < 4; mt++)
#pragma unroll
            for (int nt = 0; nt < 4; nt++)
#pragma unroll
                for (int i = 0; i < 4; i++) acc[mt][nt][i] = 0.0f;

        float4 av[4], bv[4];
#pragma unroll
        for (int p = 0; p < 4; p++)
            av[p] = *(const float4*)&ins[(size_t)(mBase + ra + p * 32) * DD + ca];
#pragma unroll
        for (int p = 0; p < 4; p++)
            bv[p] = *(const float4*)&Wi[(size_t)(rb + p * 8) * ND + nBase + cb];

        for (int kb = 0; kb < DD; kb += AK) {
#pragma unroll
            for (int p = 0; p < 4; p++) {
                float* d = &As[(ra + p * 32) * AS_S + ca];
                d[0] = f2tf_f(av[p].x); d[1] = f2tf_f(av[p].y);
                d[2] = f2tf_f(av[p].z); d[3] = f2tf_f(av[p].w);
            }
#pragma unroll
            for (int p = 0; p < 4; p++) {
                float* d = &Bs[(rb + p * 8) * BS_S + cb];
                d[0] = f2tf_f(bv[p].x); d[1] = f2tf_f(bv[p].y);
                d[2] = f2tf_f(bv[p].z); d[3] = f2tf_f(bv[p].w);
            }
            __syncthreads();

            if (kb + AK < DD) {
#pragma unroll
                for (int p = 0; p < 4; p++)
                    av[p] = *(const float4*)&ins[(size_t)(mBase + ra + p * 32) * DD + kb + AK + ca];
#pragma unroll
                for (int p = 0; p < 4; p++)
                    bv[p] = *(const float4*)&Wi[(size_t)(kb + AK + rb + p * 8) * ND + nBase + cb];
            }

#pragma unroll
            for (int kk = 0; kk < AK; kk += 8) {
                unsigned a[4][4];
#pragma unroll
                for (int mt = 0; mt < 4; mt++) {
                    int r0 = wm * 64 + mt * 16;
                    a[mt][0] = fu(As[(r0 + g) * AS_S + kk + tg]);
                    a[mt][1] = fu(As[(r0 + 8 + g) * AS_S + kk + tg]);
                    a[mt][2] = fu(As[(r0 + g) * AS_S + kk + 4 + tg]);
                    a[mt][3] = fu(As[(r0 + 8 + g) * AS_S + kk + 4 + tg]);
                }
                unsigned b[4][2];
#pragma unroll
                for (int nt = 0; nt < 4; nt++) {
                    int c0 = wn * 32 + nt * 8;
                    b[nt][0] = fu(Bs[(kk + tg) * BS_S + c0 + g]);
                    b[nt][1] = fu(Bs[(kk + 4 + tg) * BS_S + c0 + g]);
                }
#pragma unroll
                for (int mt = 0; mt < 4; mt++)
#pragma unroll
                    for (int nt = 0; nt < 4; nt++)
                        mma_tf32(acc[mt][nt], a[mt], b[nt]);
            }
            __syncthreads();
        }

#pragma unroll
        for (int mt = 0; mt < 4; mt++) {
#pragma unroll
            for (int nt = 0; nt < 4; nt++) {
                int col = nBase + wn * 32 + nt * 8 + 2 * tg;
                float b0 = bi[col], b1 = bi[col + 1];
                int r0 = mBase + wm * 64 + mt * 16 + g;
                float2 v0 = make_float2(acc[mt][nt][0] + b0, acc[mt][nt][1] + b1);
                float2 v1 = make_float2(acc[mt][nt][2] + b0, acc[mt][nt][3] + b1);
                *(float2*)&g_xproj[(size_t)r0 * ND + col] = v0;
                *(float2*)&g_xproj[(size_t)(r0 + 8) * ND + col] = v1;
            }
        }
        __syncthreads();
    }
}

// ---------------- fused persistent kernel ----------------
__global__ __launch_bounds__(256) void fused_kernel(
    const float* __restrict__ ins, const float* __restrict__ hiddens,
    const void* __restrict__ dones, const float* __restrict__ init_carry,
    const float* __restrict__ Wi, const float* __restrict__ Wh,
    const float* __restrict__ bi, const float* __restrict__ bhn,
    float* __restrict__ out)
{
    extern __shared__ unsigned smu[];
    int bid = blockIdx.x;
    int tid = threadIdx.x;

    int warp = tid >> 5, lane = tid & 31;

    // dones-dtype detection (first 1024 bytes; safe for smallest u8 layout)
    int dflag;
    {
        int lf = 0, li = 0;
        const float* pf = (const float*)dones;
        const int*   pi = (const int*)dones;
        for (int i = lane; i < 256; i += 32) {
            float v = pf[i];
            if (!(v == 0.0f || v == 1.0f)) lf = 1;
            int w = pi[i];
            if (!(w == 0 || w == 1)) li = 1;
        }
        lf = __any_sync(0xffffffffu, lf);
        li = __any_sync(0xffffffffu, li);
        dflag = (!lf) ? 2 : ((!li) ? 0 : 1);
    }

    // recurrence geometry (valid when bid < RG)
    int f0 = bid * FPC;
    int sub = bid & 1;            // which half of the k-group this CTA's features are
    int kgown = bid >> 1;         // k-group (fragment block) index

    // per-thread epilogue slot: one (b, feature-pair)
    int b_s = tid >> 2;
    int jp_s = (tid & 3) << 1;                    // 0,2,4,6
    int idx_s;
    {
        int half = (b_s >> 3) & 1, g_s = b_s & 7, wm_s = b_s >> 4;
        int tg_s = jp_s >> 1;
        idx_s = wm_s * 128 + g_s * 16 + tg_s * 4 + sub * 2 + half;
    }

    // prologue: h_eff[0]; carry own pair in regs; write ring[0] slice
    float he0 = 0.f, he1 = 0.f;
    if (bid < RG) {
        int b = b_s, f = f0 + jp_s;
        bool dn = get_done(dones, b, dflag);
        float v0 = dn ? hiddens[(size_t)b * DD + f]     : init_carry[(size_t)b * DD + f];
        float v1 = dn ? hiddens[(size_t)b * DD + f + 1] : init_carry[(size_t)b * DD + f + 1];
        he0 = v0; he1 = v1;
        __half2 p = __floats2half2_rn(v0, v1);
        g_hfrag[0][kgown * 512 + idx_s] = *(unsigned*)&p;
    }

    // ---------------- phase 1: everyone does xproj ----------------
    phase1_xproj((float*)smu, ins, Wi, bi, bid);

    grid_barrier(GRID_ALL);
    if (bid >= RG) return;

    // ---------------- phase 2 setup ----------------
    unsigned* ws   = smu;                       // b-frags: 64 kg x 3 ntw x 32 lanes x 2 u32
    float*    ps   = (float*)&smu[OFF_PS];
    float*    ps2  = (float*)&smu[OFF_PS2];
    float*    bh_s = (float*)&smu[OFF_BH];

    int wm = warp & 3;            // m-tile (16 rows)
    int kh = warp >> 2;           // k-half: kkg 0..31 / 32..63
    int g = lane >> 2, tg = lane & 3;

    // one-time: W_h slice (24 cols) as fragment-major fp16 b-frags
    for (int idx = tid; idx < 64 * 3 * 32; idx += 256) {
        int l = idx & 31;
        int ntw = (idx >> 5) % 3;
        int kg = idx / 96;
        int c = ntw * 8 + (l >> 2);           // 0..23
        int gate = c >> 3, j = c & 7;
        size_t colg = (size_t)gate * DD + f0 + j;
        int k0 = kg * 16 + 2 * (l & 3);
        float w0 = Wh[(size_t)k0 * ND + colg];
        float w1 = Wh[(size_t)(k0 + 1) * ND + colg];
        float w2 = Wh[(size_t)(k0 + 8) * ND + colg];
        float w3 = Wh[(size_t)(k0 + 9) * ND + colg];
        __half2 p0 = __floats2half2_rn(w0, w1);
        __half2 p1 = __floats2half2_rn(w2, w3);
        ws[(size_t)idx * 2 + 0] = *(unsigned*)&p0;
        ws[(size_t)idx * 2 + 1] = *(unsigned*)&p1;
    }
    if (tid < 8) bh_s[tid] = bhn[f0 + tid];
    __syncthreads();

    int abase = wm * 32 + lane;     // uint4 index within a kkg block
    int khbase = kh * 32;
    int mycnt = (bid & 15) * 32;

    for (int t = 0; t < TT; t++) {
        const uint4* rbuf = (const uint4*)&g_hfrag[t & 1][0];
        unsigned* wr = &g_hfrag[(t + 1) & 1][kgown * 512];

        float acc[3][4];
#pragma unroll
        for (int n = 0; n < 3; n++)
#pragma unroll
            for (int i = 0; i < 4; i++) acc[n][i] = 0.0f;

        // epilogue operand prefetch FIRST (independent of h ring; hides under wait)
        float2 xrv, xzv, xnv, hvv;
        int dnp;
        {
            int b = b_s;
            size_t base = ((size_t)t * BB + b) * ND + f0 + jp_s;
            xrv = *(const float2*)&g_xproj[base];
            xzv = *(const float2*)&g_xproj[base + DD];
            xnv = *(const float2*)&g_xproj[base + 2 * DD];
            if (t < TT - 1) {
                dnp = get_done(dones, (t + 1) * BB + b, dflag) ? 1 : 0;
                hvv = *(const float2*)&hiddens[((size_t)(t + 1) * BB + b) * DD + f0 + jp_s];
            } else { dnp = 0; hvv = make_float2(0.f, 0.f); }
        }

        // wait: ring[t&1] complete (all CTAs arrived for step t)
        if (t > 0) {
            if (tid < 16) {
                unsigned need = 8u * (unsigned)t;
                while (ld_acq(&g_cnt16[tid * 32]) < need) { }
            }
            __syncthreads();
        }

        uint4 bufa[2][8];
#define LDCH(d, ch) { \
    _Pragma("unroll") \
    for (int u = 0; u < 8; u++) \
        bufa[d][u] = __ldcg(&rbuf[(khbase + (ch) * 8 + u) * 128 + abase]); }

        LDCH(0, 0);

        // mainloop: 4 chunks x 8 kkg, double-buffered LDG, no syncthreads
#pragma unroll
        for (int ch = 0; ch < 4; ch++) {
            if (ch < 3) LDCH((ch + 1) & 1, ch + 1);
#pragma unroll
            for (int u = 0; u < 8; u++) {
                int kkg = khbase + ch * 8 + u;
                uint4 a4 = bufa[ch & 1][u];
#pragma unroll
                for (int ntw = 0; ntw < 3; ntw++) {
                    uint2 b2 = *(const uint2*)&ws[(size_t)((kkg * 3 + ntw) * 32 + lane) * 2];
                    mma_f16(acc[ntw], (const unsigned*)&a4, (const unsigned*)&b2);
                }
            }
        }
#undef LDCH

        // partial-sum stores: kh=0 -> ps, kh=1 -> ps2
        {
            float* dst = kh ? ps2 : ps;
            int r0 = wm * 16 + g;
#pragma unroll
            for (int ntw = 0; ntw < 3; ntw++) {
                int c0 = ntw * 8 + 2 * tg;
                dst[r0 * PS2_S + c0]           = acc[ntw][0];
                dst[r0 * PS2_S + c0 + 1]       = acc[ntw][1];
                dst[(r0 + 8) * PS2_S + c0]     = acc[ntw][2];
                dst[(r0 + 8) * PS2_S + c0 + 1] = acc[ntw][3];
            }
        }
        __syncthreads();

        // gates (one feature-pair per thread)
        float h0, h1;
        {
            int b = b_s, j = jp_s;
            int rb0 = b * PS2_S;
            float pr0 = ps[rb0 + j]          + ps2[rb0 + j];
            float pr1 = ps[rb0 + j + 1]      + ps2[rb0 + j + 1];
            float pz0 = ps[rb0 + 8 + j]      + ps2[rb0 + 8 + j];
            float pz1 = ps[rb0 + 8 + j + 1]  + ps2[rb0 + 8 + j + 1];
            float pn0 = ps[rb0 + 16 + j]     + ps2[rb0 + 16 + j];
            float pn1 = ps[rb0 + 16 + j + 1] + ps2[rb0 + 16 + j + 1];

            float r0 = sigmoidf_(xrv.x + pr0);
            float r1 = sigmoidf_(xrv.y + pr1);
            float z0 = sigmoidf_(xzv.x + pz0);
            float z1 = sigmoidf_(xzv.y + pz1);
            float n0 = tanhf(xnv.x + r0 * (pn0 + bh_s[j]));
            float n1 = tanhf(xnv.y + r1 * (pn1 + bh_s[j + 1]));
            h0 = (1.0f - z0) * n0 + z0 * he0;
            h1 = (1.0f - z1) * n1 + z1 * he1;

            if (t < TT - 1) {
                float nv0 = dnp ? hvv.x : h0;
                float nv1 = dnp ? hvv.y : h1;
                __half2 p = __floats2half2_rn(nv0, nv1);
                wr[idx_s] = *(unsigned*)&p;
                he0 = nv0; he1 = nv1;
            }
        }
        __syncthreads();

        // arrive (h ring for t+1 is published) — then do DRAM output stores
        if (t < TT - 1 && tid == 0) red_rel_add(&g_cnt16[mycnt], 1u);

        {
            int b = b_s, f = f0 + jp_s;
            *(float2*)&out[BB * DD + ((size_t)t * BB + b) * DD + f] = make_float2(h0, h1);  // ys
            if (t == TT - 1)
                *(float2*)&out[(size_t)b * DD + f] = make_float2(h0, h1);                    // final_carry
        }
    }
}

// ---------------- launch ----------------
extern "C" void kernel_launch(void* const* d_in, const int* in_sizes, int n_in,
                              void* d_out, int out_size) {
    const float* ins        = (const float*)d_in[0];
    const float* hiddens    = (const float*)d_in[1];
    const void*  dones      = (const void*)d_in[2];
    const float* init_carry = (const float*)d_in[3];
    const float* Wi         = (const float*)d_in[4];
    const float* Wh         = (const float*)d_in[5];
    const float* bi         = (const float*)d_in[6];
    const float* bhn        = (const float*)d_in[7];
    float* out = (float*)d_out;

    static int smem_set = 0;
    if (!smem_set) {
        cudaFuncSetAttribute(fused_kernel,
            cudaFuncAttributeMaxDynamicSharedMemorySize, SMEM_BYTES);
        smem_set = 1;
    }

    reset_kernel<<<1, 32>>>();
    fused_kernel<<<GRID_ALL, 256, SMEM_BYTES>>>(
        ins, hiddens, dones, init_carry, Wi, Wh, bi, bhn, out);
}

// round 15
// speedup vs baseline: 3.3555x; 1.1678x over previous
#include <cuda_runtime.h>
#include <cuda_fp16.h>
#include <math.h>

#define TT 256
#define BB 64
#define DD 1024
#define ND (3*DD)        // 3072
#define MTOT (TT*BB)     // 16384

#define RG 128           // phase-2 recurrence CTAs
#define GRID_ALL 148     // one full wave
#define NTILE_N (ND / 128)        // 24
#define NTILE_M (MTOT / 128)      // 128
#define NTILES (NTILE_M * NTILE_N) // 3072

// ---------------- scratch ----------------
__device__ float g_xproj[(size_t)MTOT * ND];
// h ring in fp16 A-fragment layout: [2][64 kkg][512 u32]
__device__ __align__(16) unsigned g_hfrag[2][64 * 512];
__device__ unsigned g_count;
__device__ unsigned g_release;
__device__ unsigned g_cnt16[16 * 32];   // distributed arrival counters (128B apart)

// ---------------- primitives ----------------
__device__ __forceinline__ unsigned fu(float x) { return __float_as_uint(x); }

__device__ __forceinline__ unsigned h2pack(float a, float b) {
    __half2 p = __floats2half2_rn(a, b);
    return *(unsigned*)&p;
}

__device__ __forceinline__ unsigned ld_acq(const unsigned* p) {
    unsigned v;
    asm volatile("ld.acquire.gpu.global.b32 %0, [%1];" : "=r"(v) : "l"(p) : "memory");
    return v;
}
__device__ __forceinline__ void red_rel_add(unsigned* p, unsigned v) {
    asm volatile("red.release.gpu.global.add.u32 [%0], %1;" :: "l"(p), "r"(v) : "memory");
}
__device__ __forceinline__ unsigned atom_rel_add(unsigned* p, unsigned v) {
    unsigned old;
    asm volatile("atom.release.gpu.global.add.u32 %0, [%1], %2;"
                 : "=r"(old) : "l"(p), "r"(v) : "memory");
    return old;
}
__device__ __forceinline__ void st_rel(unsigned* p, unsigned v) {
    asm volatile("st.release.gpu.global.b32 [%0], %1;" :: "l"(p), "r"(v) : "memory");
}

__device__ __forceinline__ void mma_f16(float c[4], const unsigned a[4], const unsigned b[2]) {
    asm volatile(
        "mma.sync.aligned.m16n8k16.row.col.f32.f16.f16.f32 "
        "{%0,%1,%2,%3}, {%4,%5,%6,%7}, {%8,%9}, {%0,%1,%2,%3};\n"
        : "+f"(c[0]), "+f"(c[1]), "+f"(c[2]), "+f"(c[3])
        : "r"(a[0]), "r"(a[1]), "r"(a[2]), "r"(a[3]),
          "r"(b[0]), "r"(b[1]));
}

__device__ __forceinline__ bool get_done(const void* p, int idx, int flag) {
    if (flag == 1) return ((const unsigned char*)p)[idx] != 0;
    if (flag == 0) return ((const int*)p)[idx] != 0;
    return ((const float*)p)[idx] != 0.0f;
}
__device__ __forceinline__ float sigmoidf_(float x) {
    return 1.0f / (1.0f + __expf(-x));
}

// ---------------- reset ----------------
__global__ void reset_kernel() {
    int t = threadIdx.x;
    if (t == 0) { g_count = 0u; g_release = 0u; }
    if (t < 16) g_cnt16[t * 32] = 0u;
}

// ---------------- geometry ----------------
#define FPC 8            // features per recurrence CTA

// phase-1 fp16 smem (u32 words): Ah 128*20 | Bp 16*132
#define AH_W 20
#define BP_W 132
#define P1_AH 0
#define P1_BP (128 * AH_W)           // 2560

// phase-2 smem (u32 words): ws 12288 | ps 64*26 | ps2 64*26 | bh 8
#define WS_U32  12288
#define PS2_S   26
#define OFF_PS  WS_U32
#define OFF_PS2 (WS_U32 + BB * PS2_S)
#define OFF_BH  (WS_U32 + 2 * BB * PS2_S)
#define SMEM_WORDS (OFF_BH + 8)
#define SMEM_BYTES (SMEM_WORDS * 4)          // 62,496 B (covers phase-1's 18.7 KB too)

__device__ __forceinline__ void grid_barrier(unsigned expected) {
    __syncthreads();
    if (threadIdx.x == 0) {
        unsigned prev = atom_rel_add(&g_count, 1u);
        if (prev + 1u == expected) {
            st_rel(&g_release, expected);
        } else {
            while (ld_acq(&g_release) < expected) { }
        }
    }
    __syncthreads();
}

// ---------------- phase 1: xproj tiles (fp16 m16n8k16, all CTAs) ----------------
// C[16384,3072] = ins[16384,1024] @ Wi[1024,3072] + bi, fp32 accum.
__device__ void phase1_xproj(unsigned* smu, const float* __restrict__ ins,
                             const float* __restrict__ Wi,
                             const float* __restrict__ bi, int bid)
{
    unsigned* Ah = &smu[P1_AH];     // A tile: 128 rows x 32 k (half), stride 20 u32/row
    unsigned* Bp = &smu[P1_BP];     // B tile: 16 q x 128 cols, u32 = (B[2q][c], B[2q+1][c])

    int tid  = threadIdx.x;
    int warp = tid >> 5, lane = tid & 31;
    int wm = warp >> 2, wn = warp & 3;   // warp tile: rows wm*64.., cols wn*32..
    int g = lane >> 2, tg = lane & 3;

    // A staging: thread reads float4 at row ra+p*32, k-offset ca
    int ra = tid >> 3;            // 0..31
    int ca = (tid & 7) << 2;      // 0..28 (k halves)
    // B staging: thread handles q = qb, cols cb..cb+7 (rows 2qb, 2qb+1)
    int qb = tid >> 4;            // 0..15
    int cb = (tid & 15) << 3;     // 0..120

    for (int tile = bid; tile < NTILES; tile += GRID_ALL) {
        int mb = tile / NTILE_N, nb = tile % NTILE_N;
        int mBase = mb * 128, nBase = nb * 128;

        float acc[4][4][4];
#pragma unroll
        for (int mt = 0; mt < 4; mt++)
#pragma unroll
            for (int nt = 0; nt < 4; nt++)
#pragma unroll
                for (int i = 0; i < 4; i++) acc[mt][nt][i] = 0.0f;

        float4 av[4], bv[4];
#pragma unroll
        for (int p = 0; p < 4; p++)
            av[p] = *(const float4*)&ins[(size_t)(mBase + ra + p * 32) * DD + ca];
#pragma unroll
        for (int j = 0; j < 4; j++)
            bv[j] = *(const float4*)&Wi[(size_t)(2 * qb + (j >> 1)) * ND + nBase + cb + (j & 1) * 4];

        for (int kb = 0; kb < DD; kb += 32) {
            // commit A: packed half2 pairs
#pragma unroll
            for (int p = 0; p < 4; p++) {
                int w = (ra + p * 32) * AH_W + (ca >> 1);
                Ah[w]     = h2pack(av[p].x, av[p].y);
                Ah[w + 1] = h2pack(av[p].z, av[p].w);
            }
            // commit B: k-pair packed words, uint4 stores
            {
                uint4 w0, w1;
                w0.x = h2pack(bv[0].x, bv[2].x); w0.y = h2pack(bv[0].y, bv[2].y);
                w0.z = h2pack(bv[0].z, bv[2].z); w0.w = h2pack(bv[0].w, bv[2].w);
                w1.x = h2pack(bv[1].x, bv[3].x); w1.y = h2pack(bv[1].y, bv[3].y);
                w1.z = h2pack(bv[1].z, bv[3].z); w1.w = h2pack(bv[1].w, bv[3].w);
                *(uint4*)&Bp[qb * BP_W + cb]     = w0;
                *(uint4*)&Bp[qb * BP_W + cb + 4] = w1;
            }
            __syncthreads();

            // prefetch next k-block
            if (kb + 32 < DD) {
#pragma unroll
                for (int p = 0; p < 4; p++)
                    av[p] = *(const float4*)&ins[(size_t)(mBase + ra + p * 32) * DD + kb + 32 + ca];
#pragma unroll
                for (int j = 0; j < 4; j++)
                    bv[j] = *(const float4*)&Wi[(size_t)(kb + 32 + 2 * qb + (j >> 1)) * ND + nBase + cb + (j & 1) * 4];
            }

#pragma unroll
            for (int kkq = 0; kkq < 2; kkq++) {
                unsigned a[4][4];
#pragma unroll
                for (int mt = 0; mt < 4; mt++) {
                    int r0 = wm * 64 + mt * 16;
                    int base0 = (r0 + g) * AH_W + kkq * 8 + tg;
                    int base1 = (r0 + 8 + g) * AH_W + kkq * 8 + tg;
                    a[mt][0] = Ah[base0];
                    a[mt][1] = Ah[base1];
                    a[mt][2] = Ah[base0 + 4];
                    a[mt][3] = Ah[base1 + 4];
                }
                unsigned b[4][2];
#pragma unroll
                for (int nt = 0; nt < 4; nt++) {
                    int c0 = wn * 32 + nt * 8 + g;
                    int q0 = kkq * 8 + tg;
                    b[nt][0] = Bp[q0 * BP_W + c0];
                    b[nt][1] = Bp[(q0 + 4) * BP_W + c0];
                }
#pragma unroll
                for (int mt = 0; mt < 4; mt++)
#pragma unroll
                    for (int nt = 0; nt < 4; nt++)
                        mma_f16(acc[mt][nt], a[mt], b[nt]);
            }
            __syncthreads();
        }

        // epilogue: bias + store (C-frag layout identical to k8 version)
#pragma unroll
        for (int mt = 0; mt < 4; mt++) {
#pragma unroll
            for (int nt = 0; nt < 4; nt++) {
                int col = nBase + wn * 32 + nt * 8 + 2 * tg;
                float b0 = bi[col], b1 = bi[col + 1];
                int r0 = mBase + wm * 64 + mt * 16 + g;
                float2 v0 = make_float2(acc[mt][nt][0] + b0, acc[mt][nt][1] + b1);
                float2 v1 = make_float2(acc[mt][nt][2] + b0, acc[mt][nt][3] + b1);
                *(float2*)&g_xproj[(size_t)r0 * ND + col] = v0;
                *(float2*)&g_xproj[(size_t)(r0 + 8) * ND + col] = v1;
            }
        }
        __syncthreads();
    }
}

// ---------------- fused persistent kernel ----------------
__global__ __launch_bounds__(256) void fused_kernel(
    const float* __restrict__ ins, const float* __restrict__ hiddens,
    const void* __restrict__ dones, const float* __restrict__ init_carry,
    const float* __restrict__ Wi, const float* __restrict__ Wh,
    const float* __restrict__ bi, const float* __restrict__ bhn,
    float* __restrict__ out)
{
    extern __shared__ unsigned smu[];
    int bid = blockIdx.x;
    int tid = threadIdx.x;

    int warp = tid >> 5, lane = tid & 31;

    // dones-dtype detection (first 1024 bytes; safe for smallest u8 layout)
    int dflag;
    {
        int lf = 0, li = 0;
        const float* pf = (const float*)dones;
        const int*   pi = (const int*)dones;
        for (int i = lane; i < 256; i += 32) {
            float v = pf[i];
            if (!(v == 0.0f || v == 1.0f)) lf = 1;
            int w = pi[i];
            if (!(w == 0 || w == 1)) li = 1;
        }
        lf = __any_sync(0xffffffffu, lf);
        li = __any_sync(0xffffffffu, li);
        dflag = (!lf) ? 2 : ((!li) ? 0 : 1);
    }

    // recurrence geometry (valid when bid < RG)
    int f0 = bid * FPC;
    int sub = bid & 1;            // which half of the k-group this CTA's features are
    int kgown = bid >> 1;         // k-group (fragment block) index

    // per-thread epilogue slot: one (b, feature-pair)
    int b_s = tid >> 2;
    int jp_s = (tid & 3) << 1;                    // 0,2,4,6
    int idx_s;
    {
        int half = (b_s >> 3) & 1, g_s = b_s & 7, wm_s = b_s >> 4;
        int tg_s = jp_s >> 1;
        idx_s = wm_s * 128 + g_s * 16 + tg_s * 4 + sub * 2 + half;
    }

    // prologue: h_eff[0]; carry own pair in regs; write ring[0] slice
    float he0 = 0.f, he1 = 0.f;
    if (bid < RG) {
        int b = b_s, f = f0 + jp_s;
        bool dn = get_done(dones, b, dflag);
        float v0 = dn ? hiddens[(size_t)b * DD + f]     : init_carry[(size_t)b * DD + f];
        float v1 = dn ? hiddens[(size_t)b * DD + f + 1] : init_carry[(size_t)b * DD + f + 1];
        he0 = v0; he1 = v1;
        g_hfrag[0][kgown * 512 + idx_s] = h2pack(v0, v1);
    }

    // ---------------- phase 1: everyone does xproj ----------------
    phase1_xproj(smu, ins, Wi, bi, bid);

    grid_barrier(GRID_ALL);
    if (bid >= RG) return;

    // ---------------- phase 2 setup ----------------
    unsigned* ws   = smu;                       // b-frags: 64 kg x 3 ntw x 32 lanes x 2 u32
    float*    ps   = (float*)&smu[OFF_PS];
    float*    ps2  = (float*)&smu[OFF_PS2];
    float*    bh_s = (float*)&smu[OFF_BH];

    int wm = warp & 3;            // m-tile (16 rows)
    int kh = warp >> 2;           // k-half: kkg 0..31 / 32..63
    int g = lane >> 2, tg = lane & 3;

    // one-time: W_h slice (24 cols) as fragment-major fp16 b-frags
    for (int idx = tid; idx < 64 * 3 * 32; idx += 256) {
        int l = idx & 31;
        int ntw = (idx >> 5) % 3;
        int kg = idx / 96;
        int c = ntw * 8 + (l >> 2);           // 0..23
        int gate = c >> 3, j = c & 7;
        size_t colg = (size_t)gate * DD + f0 + j;
        int k0 = kg * 16 + 2 * (l & 3);
        float w0 = Wh[(size_t)k0 * ND + colg];
        float w1 = Wh[(size_t)(k0 + 1) * ND + colg];
        float w2 = Wh[(size_t)(k0 + 8) * ND + colg];
        float w3 = Wh[(size_t)(k0 + 9) * ND + colg];
        ws[(size_t)idx * 2 + 0] = h2pack(w0, w1);
        ws[(size_t)idx * 2 + 1] = h2pack(w2, w3);
    }
    if (tid < 8) bh_s[tid] = bhn[f0 + tid];
    __syncthreads();

    int abase = wm * 32 + lane;     // uint4 index within a kkg block
    int khbase = kh * 32;
    int mycnt = (bid & 15) * 32;

    for (int t = 0; t < TT; t++) {
        const uint4* rbuf = (const uint4*)&g_hfrag[t & 1][0];
        unsigned* wr = &g_hfrag[(t + 1) & 1][kgown * 512];

        float acc[3][4];
#pragma unroll
        for (int n = 0; n < 3; n++)
#pragma unroll
            for (int i = 0; i < 4; i++) acc[n][i] = 0.0f;

        // epilogue operand prefetch FIRST (independent of h ring; hides under wait)
        float2 xrv, xzv, xnv, hvv;
        int dnp;
        {
            int b = b_s;
            size_t base = ((size_t)t * BB + b) * ND + f0 + jp_s;
            xrv = *(const float2*)&g_xproj[base];
            xzv = *(const float2*)&g_xproj[base + DD];
            xnv = *(const float2*)&g_xproj[base + 2 * DD];
            if (t < TT - 1) {
                dnp = get_done(dones, (t + 1) * BB + b, dflag) ? 1 : 0;
                hvv = *(const float2*)&hiddens[((size_t)(t + 1) * BB + b) * DD + f0 + jp_s];
            } else { dnp = 0; hvv = make_float2(0.f, 0.f); }
        }

        // wait: ring[t&1] complete (all CTAs arrived for step t)
        if (t > 0) {
            if (tid < 16) {
                unsigned need = 8u * (unsigned)t;
                while (ld_acq(&g_cnt16[tid * 32]) < need) { }
            }
            __syncthreads();
        }

        uint4 bufa[2][8];
#define LDCH(d, ch) { \
    _Pragma("unroll") \
    for (int u = 0; u < 8; u++) \
        bufa[d][u] = __ldcg(&rbuf[(khbase + (ch) * 8 + u) * 128 + abase]); }

        LDCH(0, 0);

        // mainloop: 4 chunks x 8 kkg, double-buffered LDG, no syncthreads
#pragma unroll
        for (int ch = 0; ch < 4; ch++) {
            if (ch < 3) LDCH((ch + 1) & 1, ch + 1);
#pragma unroll
            for (int u = 0; u < 8; u++) {
                int kkg = khbase + ch * 8 + u;
                uint4 a4 = bufa[ch & 1][u];
#pragma unroll
                for (int ntw = 0; ntw < 3; ntw++) {
                    uint2 b2 = *(const uint2*)&ws[(size_t)((kkg * 3 + ntw) * 32 + lane) * 2];
                    mma_f16(acc[ntw], (const unsigned*)&a4, (const unsigned*)&b2);
                }
            }
        }
#undef LDCH

        // partial-sum stores: kh=0 -> ps, kh=1 -> ps2
        {
            float* dst = kh ? ps2 : ps;
            int r0 = wm * 16 + g;
#pragma unroll
            for (int ntw = 0; ntw < 3; ntw++) {
                int c0 = ntw * 8 + 2 * tg;
                dst[r0 * PS2_S + c0]           = acc[ntw][0];
                dst[r0 * PS2_S + c0 + 1]       = acc[ntw][1];
                dst[(r0 + 8) * PS2_S + c0]     = acc[ntw][2];
                dst[(r0 + 8) * PS2_S + c0 + 1] = acc[ntw][3];
            }
        }
        __syncthreads();

        // gates (one feature-pair per thread)
        float h0, h1;
        {
            int b = b_s, j = jp_s;
            int rb0 = b * PS2_S;
            float pr0 = ps[rb0 + j]          + ps2[rb0 + j];
            float pr1 = ps[rb0 + j + 1]      + ps2[rb0 + j + 1];
            float pz0 = ps[rb0 + 8 + j]      + ps2[rb0 + 8 + j];
            float pz1 = ps[rb0 + 8 + j + 1]  + ps2[rb0 + 8 + j + 1];
            float pn0 = ps[rb0 + 16 + j]     + ps2[rb0 + 16 + j];
            float pn1 = ps[rb0 + 16 + j + 1] + ps2[rb0 + 16 + j + 1];

            float r0 = sigmoidf_(xrv.x + pr0);
            float r1 = sigmoidf_(xrv.y + pr1);
            float z0 = sigmoidf_(xzv.x + pz0);
            float z1 = sigmoidf_(xzv.y + pz1);
            float n0 = tanhf(xnv.x + r0 * (pn0 + bh_s[j]));
            float n1 = tanhf(xnv.y + r1 * (pn1 + bh_s[j + 1]));
            h0 = (1.0f - z0) * n0 + z0 * he0;
            h1 = (1.0f - z1) * n1 + z1 * he1;

            if (t < TT - 1) {
                float nv0 = dnp ? hvv.x : h0;
                float nv1 = dnp ? hvv.y : h1;
                wr[idx_s] = h2pack(nv0, nv1);
                he0 = nv0; he1 = nv1;
            }
        }
        __syncthreads();

        // arrive (h ring for t+1 is published) — then do DRAM output stores
        if (t < TT - 1 && tid == 0) red_rel_add(&g_cnt16[mycnt], 1u);

        {
            int b = b_s, f = f0 + jp_s;
            *(float2*)&out[BB * DD + ((size_t)t * BB + b) * DD + f] = make_float2(h0, h1);  // ys
            if (t == TT - 1)
                *(float2*)&out[(size_t)b * DD + f] = make_float2(h0, h1);                    // final_carry
        }
    }
}

// ---------------- launch ----------------
extern "C" void kernel_launch(void* const* d_in, const int* in_sizes, int n_in,
                              void* d_out, int out_size) {
    const float* ins        = (const float*)d_in[0];
    const float* hiddens    = (const float*)d_in[1];
    const void*  dones      = (const void*)d_in[2];
    const float* init_carry = (const float*)d_in[3];
    const float* Wi         = (const float*)d_in[4];
    const float* Wh         = (const float*)d_in[5];
    const float* bi         = (const float*)d_in[6];
    const float* bhn        = (const float*)d_in[7];
    float* out = (float*)d_out;

    static int smem_set = 0;
    if (!smem_set) {
        cudaFuncSetAttribute(fused_kernel,
            cudaFuncAttributeMaxDynamicSharedMemorySize, SMEM_BYTES);
        smem_set = 1;
    }

    reset_kernel<<<1, 32>>>();
    fused_kernel<<<GRID_ALL, 256, SMEM_BYTES>>>(
        ins, hiddens, dones, init_carry, Wi, Wh, bi, bhn, out);
}